// round 4
// baseline (speedup 1.0000x reference)
#include <cuda_runtime.h>
#include <cstdint>
#include <math.h>

// Problem constants
#define BATCH   2
#define TSEQ    2048
#define CDIM    1024
#define HEADS   16
#define HD      64
#define BT      (BATCH * TSEQ)          // 4096 rows
#define QKVDIM  (3 * CDIM)              // 3072

// Scratch (allocation-free rule: __device__ globals)
__device__ float g_qkv[(size_t)BT * QKVDIM];   // [4096, 3072]
__device__ float g_ao [(size_t)BT * CDIM];     // [4096, 1024]

__device__ __forceinline__ uint32_t f2tf32(float v) {
    uint32_t u;
    asm("cvt.rna.tf32.f32 %0, %1;" : "=r"(u) : "f"(v));
    return u;
}

__device__ __forceinline__ void mma_tf32(
    float& c0, float& c1, float& c2, float& c3,
    uint32_t a0, uint32_t a1, uint32_t a2, uint32_t a3,
    uint32_t b0, uint32_t b1)
{
    asm volatile(
        "mma.sync.aligned.m16n8k8.row.col.f32.tf32.tf32.f32 "
        "{%0,%1,%2,%3}, {%4,%5,%6,%7}, {%8,%9}, {%0,%1,%2,%3};"
        : "+f"(c0), "+f"(c1), "+f"(c2), "+f"(c3)
        : "r"(a0), "r"(a1), "r"(a2), "r"(a3), "r"(b0), "r"(b1));
}

// ---------------------------------------------------------------------------
// TF32 mma.sync GEMM: C[M,N] = A[M,K] @ B[N,K]^T  (row-major, K contiguous)
// 128x128 CTA tile, BK=32. 8 warps in a 4(M)x2(N) grid; warp tile 32x64.
// m16n8k8 atoms: 2 M-tiles x 8 N-tiles = 16 mma per k-step, 4 k-steps/chunk.
// Smem stride 36 floats -> fragment LDS is bank-conflict-free.
// ---------------------------------------------------------------------------
#define TM  128
#define TN  128
#define BKF 32
#define SSTR 36

__global__ __launch_bounds__(256, 2) void gemm_tf32_nt(
    const float* __restrict__ A, const float* __restrict__ B,
    float* __restrict__ C, int M, int N, int K)
{
    __shared__ float As[TM][SSTR];
    __shared__ float Bs[TN][SSTR];

    const int tid  = threadIdx.x;
    const int wid  = tid >> 5;
    const int lane = tid & 31;
    const int g = lane >> 2;          // 0..7  (fragment row group)
    const int t = lane & 3;           // 0..3  (fragment col group)
    const int wm = (wid & 3) * 32;    // warp M offset in tile
    const int wn = (wid >> 2) * 64;   // warp N offset in tile
    const int m0 = blockIdx.y * TM;
    const int n0 = blockIdx.x * TN;

    float c[2][8][4];
#pragma unroll
    for (int mi = 0; mi < 2; mi++)
#pragma unroll
        for (int ni = 0; ni < 8; ni++)
#pragma unroll
            for (int r = 0; r < 4; r++) c[mi][ni][r] = 0.0f;

    for (int k0 = 0; k0 < K; k0 += BKF) {
        // Load A,B chunks: 128 rows x 8 float4 each; 4 iters per thread.
#pragma unroll
        for (int i = 0; i < 4; i++) {
            int e   = tid + i * 256;       // 0..1023
            int row = e >> 3;
            int q   = (e & 7) * 4;
            float4 va = *(const float4*)(A + (size_t)(m0 + row) * K + k0 + q);
            float4 vb = *(const float4*)(B + (size_t)(n0 + row) * K + k0 + q);
            *(uint4*)&As[row][q] = make_uint4(f2tf32(va.x), f2tf32(va.y),
                                              f2tf32(va.z), f2tf32(va.w));
            *(uint4*)&Bs[row][q] = make_uint4(f2tf32(vb.x), f2tf32(vb.y),
                                              f2tf32(vb.z), f2tf32(vb.w));
        }
        __syncthreads();

#pragma unroll
        for (int kk = 0; kk < 4; kk++) {
            const int kb = kk * 8;
            uint32_t a[2][4];
#pragma unroll
            for (int mi = 0; mi < 2; mi++) {
                const float* ar0 = &As[wm + mi * 16 + g][kb + t];
                const float* ar1 = &As[wm + mi * 16 + g + 8][kb + t];
                a[mi][0] = __float_as_uint(ar0[0]);
                a[mi][1] = __float_as_uint(ar1[0]);
                a[mi][2] = __float_as_uint(ar0[4]);
                a[mi][3] = __float_as_uint(ar1[4]);
            }
            uint32_t b[8][2];
#pragma unroll
            for (int ni = 0; ni < 8; ni++) {
                const float* br = &Bs[wn + ni * 8 + g][kb + t];
                b[ni][0] = __float_as_uint(br[0]);
                b[ni][1] = __float_as_uint(br[4]);
            }
#pragma unroll
            for (int mi = 0; mi < 2; mi++)
#pragma unroll
                for (int ni = 0; ni < 8; ni++)
                    mma_tf32(c[mi][ni][0], c[mi][ni][1], c[mi][ni][2], c[mi][ni][3],
                             a[mi][0], a[mi][1], a[mi][2], a[mi][3],
                             b[ni][0], b[ni][1]);
        }
        __syncthreads();
    }

    // Epilogue: c0,c1 -> (row, 2t..2t+1); c2,c3 -> (row+8, ...)
#pragma unroll
    for (int mi = 0; mi < 2; mi++) {
        const int row = m0 + wm + mi * 16 + g;
#pragma unroll
        for (int ni = 0; ni < 8; ni++) {
            const int col = n0 + wn + ni * 8 + 2 * t;
            *(float2*)(C + (size_t)row * N + col) =
                make_float2(c[mi][ni][0], c[mi][ni][1]);
            *(float2*)(C + (size_t)(row + 8) * N + col) =
                make_float2(c[mi][ni][2], c[mi][ni][3]);
        }
    }
}

// ---------------------------------------------------------------------------
// RoPE in-place on q and k thirds of g_qkv. Interleaved pairs (2i, 2i+1).
// ---------------------------------------------------------------------------
__global__ __launch_bounds__(256) void rope_kernel(
    float* __restrict__ qkv, const float* __restrict__ cs,
    const float* __restrict__ sn)
{
    const int total = BT * HEADS * (HD / 2);   // 2,097,152
    for (int idx = blockIdx.x * blockDim.x + threadIdx.x; idx < total;
         idx += gridDim.x * blockDim.x) {
        int i   = idx & 31;
        int h   = (idx >> 5) & 15;
        int row = idx >> 9;
        int t   = row & (TSEQ - 1);
        float c = cs[t * 32 + i];
        float s = sn[t * 32 + i];
        float* q = qkv + (size_t)row * QKVDIM + h * HD + 2 * i;
        float2 qv = *(float2*)q;
        *(float2*)q = make_float2(qv.x * c - qv.y * s, qv.x * s + qv.y * c);
        float* k = q + CDIM;
        float2 kv = *(float2*)k;
        *(float2*)k = make_float2(kv.x * c - kv.y * s, kv.x * s + kv.y * c);
    }
}

// ---------------------------------------------------------------------------
// Causal flash attention, fp32. 64x64 tiles, D=64, 256 threads.
// (Unchanged from the verified R2 version; R5 target for mma conversion.)
// ---------------------------------------------------------------------------
#define AM 64
#define AN 64
#define PSTR 68   // padded smem stride

__global__ __launch_bounds__(256) void attn_kernel(
    const float* __restrict__ qkv, float* __restrict__ ao)
{
    extern __shared__ float sm[];
    float* Qs = sm;                       // [64][68]
    float* Ks = Qs + AM * PSTR;           // [64][68]
    float* Ps = Ks + AN * PSTR;           // [64][68]
    float* Vs = Ps + AM * PSTR;           // [64][64]

    const int m0 = blockIdx.x * AM;
    const int h  = blockIdx.y;
    const int b  = blockIdx.z;
    const int tid = threadIdx.x;
    const int tx = tid & 15, ty = tid >> 4;
    const int r0 = ty * 4, c0 = tx * 4;

    const float* qbase = qkv + (size_t)b * TSEQ * QKVDIM + h * HD;

    for (int e = tid; e < AM * 16; e += 256) {
        int r = e >> 4, c4 = (e & 15) * 4;
        float4 v = *(const float4*)(qbase + (size_t)(m0 + r) * QKVDIM + c4);
        *(float4*)(Qs + r * PSTR + c4) = v;
    }

    float acc[4][4];
    float mi[4], li[4];
#pragma unroll
    for (int i = 0; i < 4; i++) {
        mi[i] = -1e30f; li[i] = 0.0f;
#pragma unroll
        for (int j = 0; j < 4; j++) acc[i][j] = 0.0f;
    }

    const float scale = 0.125f;  // 1/sqrt(64)

    for (int n0 = 0; n0 <= m0; n0 += AN) {
        __syncthreads();
        const float* kbase = qkv + ((size_t)b * TSEQ + n0) * QKVDIM + CDIM + h * HD;
        const float* vbase = kbase + CDIM;
        for (int e = tid; e < AN * 16; e += 256) {
            int r = e >> 4, c4 = (e & 15) * 4;
            *(float4*)(Ks + r * PSTR + c4) =
                *(const float4*)(kbase + (size_t)r * QKVDIM + c4);
            *(float4*)(Vs + r * HD + c4) =
                *(const float4*)(vbase + (size_t)r * QKVDIM + c4);
        }
        __syncthreads();

        float s[4][4];
#pragma unroll
        for (int i = 0; i < 4; i++)
#pragma unroll
            for (int j = 0; j < 4; j++) s[i][j] = 0.0f;

#pragma unroll
        for (int d = 0; d < HD; d += 4) {
            float4 a[4], kb[4];
#pragma unroll
            for (int i = 0; i < 4; i++)
                a[i] = *(const float4*)(Qs + (r0 + i) * PSTR + d);
#pragma unroll
            for (int j = 0; j < 4; j++)
                kb[j] = *(const float4*)(Ks + (c0 + j) * PSTR + d);
#pragma unroll
            for (int i = 0; i < 4; i++)
#pragma unroll
                for (int j = 0; j < 4; j++) {
                    s[i][j] = fmaf(a[i].x, kb[j].x, s[i][j]);
                    s[i][j] = fmaf(a[i].y, kb[j].y, s[i][j]);
                    s[i][j] = fmaf(a[i].z, kb[j].z, s[i][j]);
                    s[i][j] = fmaf(a[i].w, kb[j].w, s[i][j]);
                }
        }

        const bool diag = (n0 == m0);
#pragma unroll
        for (int i = 0; i < 4; i++)
#pragma unroll
            for (int j = 0; j < 4; j++) {
                s[i][j] *= scale;
                if (diag && (n0 + c0 + j) > (m0 + r0 + i)) s[i][j] = -1e30f;
            }

#pragma unroll
        for (int i = 0; i < 4; i++) {
            float mloc = fmaxf(fmaxf(s[i][0], s[i][1]), fmaxf(s[i][2], s[i][3]));
#pragma unroll
            for (int o = 8; o >= 1; o >>= 1)
                mloc = fmaxf(mloc, __shfl_xor_sync(0xffffffffu, mloc, o));
            float newm = fmaxf(mi[i], mloc);
            float alpha = __expf(mi[i] - newm);
            float p0 = __expf(s[i][0] - newm);
            float p1 = __expf(s[i][1] - newm);
            float p2 = __expf(s[i][2] - newm);
            float p3 = __expf(s[i][3] - newm);
            float rs = p0 + p1 + p2 + p3;
#pragma unroll
            for (int o = 8; o >= 1; o >>= 1)
                rs += __shfl_xor_sync(0xffffffffu, rs, o);
            li[i] = li[i] * alpha + rs;
            mi[i] = newm;
#pragma unroll
            for (int j = 0; j < 4; j++) acc[i][j] *= alpha;
            *(float4*)(Ps + (r0 + i) * PSTR + c0) = make_float4(p0, p1, p2, p3);
        }
        __syncthreads();

#pragma unroll 4
        for (int kk = 0; kk < AN; kk++) {
            float a0 = Ps[(r0 + 0) * PSTR + kk];
            float a1 = Ps[(r0 + 1) * PSTR + kk];
            float a2 = Ps[(r0 + 2) * PSTR + kk];
            float a3 = Ps[(r0 + 3) * PSTR + kk];
            float4 bv = *(const float4*)(Vs + kk * HD + c0);
            acc[0][0] = fmaf(a0, bv.x, acc[0][0]); acc[0][1] = fmaf(a0, bv.y, acc[0][1]);
            acc[0][2] = fmaf(a0, bv.z, acc[0][2]); acc[0][3] = fmaf(a0, bv.w, acc[0][3]);
            acc[1][0] = fmaf(a1, bv.x, acc[1][0]); acc[1][1] = fmaf(a1, bv.y, acc[1][1]);
            acc[1][2] = fmaf(a1, bv.z, acc[1][2]); acc[1][3] = fmaf(a1, bv.w, acc[1][3]);
            acc[2][0] = fmaf(a2, bv.x, acc[2][0]); acc[2][1] = fmaf(a2, bv.y, acc[2][1]);
            acc[2][2] = fmaf(a2, bv.z, acc[2][2]); acc[2][3] = fmaf(a2, bv.w, acc[2][3]);
            acc[3][0] = fmaf(a3, bv.x, acc[3][0]); acc[3][1] = fmaf(a3, bv.y, acc[3][1]);
            acc[3][2] = fmaf(a3, bv.z, acc[3][2]); acc[3][3] = fmaf(a3, bv.w, acc[3][3]);
        }
    }

#pragma unroll
    for (int i = 0; i < 4; i++) {
        float inv = 1.0f / li[i];
        float* orow = ao + ((size_t)b * TSEQ + m0 + r0 + i) * CDIM + h * HD + c0;
        *(float4*)orow = make_float4(acc[i][0] * inv, acc[i][1] * inv,
                                     acc[i][2] * inv, acc[i][3] * inv);
    }
}

// ---------------------------------------------------------------------------
// Host launcher
// ---------------------------------------------------------------------------
extern "C" void kernel_launch(void* const* d_in, const int* in_sizes, int n_in,
                              void* d_out, int out_size)
{
    const float* x       = (const float*)d_in[0];  // [2,2048,1024]
    const float* f_cos   = (const float*)d_in[1];  // [2048,32]
    const float* f_sin   = (const float*)d_in[2];  // [2048,32]
    const float* qkv_w   = (const float*)d_in[3];  // [3072,1024]
    const float* proj_w  = (const float*)d_in[4];  // [1024,1024]
    float* out = (float*)d_out;

    float *qkv_ptr, *ao_ptr;
    cudaGetSymbolAddress((void**)&qkv_ptr, g_qkv);
    cudaGetSymbolAddress((void**)&ao_ptr, g_ao);

    // 1) QKV projection: [4096,3072] = x @ qkv_w^T (tf32 mma.sync)
    {
        dim3 grid(QKVDIM / TN, BT / TM);
        gemm_tf32_nt<<<grid, 256>>>(x, qkv_w, qkv_ptr, BT, QKVDIM, CDIM);
    }

    // 2) RoPE in place on q,k thirds
    rope_kernel<<<2048, 256>>>(qkv_ptr, f_cos, f_sin);

    // 3) Causal attention (fp32 SIMT — next conversion target)
    {
        const int smem = (3 * AM * PSTR + AN * HD) * (int)sizeof(float);
        cudaFuncSetAttribute(attn_kernel,
                             cudaFuncAttributeMaxDynamicSharedMemorySize, smem);
        dim3 grid(TSEQ / AM, HEADS, BATCH);
        attn_kernel<<<grid, 256, smem>>>(qkv_ptr, ao_ptr);
    }

    // 4) Output projection: [4096,1024] = ao @ proj_w^T (tf32 mma.sync)
    {
        dim3 grid(CDIM / TN, BT / TM);
        gemm_tf32_nt<<<grid, 256>>>(ao_ptr, proj_w, out, BT, CDIM, CDIM);
    }
}

// round 6
// speedup vs baseline: 3.3275x; 3.3275x over previous
#include <cuda_runtime.h>
#include <cstdint>
#include <math.h>

// Problem constants
#define BATCH   2
#define TSEQ    2048
#define CDIM    1024
#define HEADS   16
#define HD      64
#define BT      (BATCH * TSEQ)          // 4096 rows
#define QKVDIM  (3 * CDIM)              // 3072

// Scratch (allocation-free rule: __device__ globals)
__device__ float g_qkv[(size_t)BT * QKVDIM];   // [4096, 3072]
__device__ float g_ao [(size_t)BT * CDIM];     // [4096, 1024]

__device__ __forceinline__ uint32_t f2tf32(float v) {
    uint32_t u;
    asm("cvt.rna.tf32.f32 %0, %1;" : "=r"(u) : "f"(v));
    return u;
}

__device__ __forceinline__ void mma_tf32(
    float& c0, float& c1, float& c2, float& c3,
    uint32_t a0, uint32_t a1, uint32_t a2, uint32_t a3,
    uint32_t b0, uint32_t b1)
{
    asm volatile(
        "mma.sync.aligned.m16n8k8.row.col.f32.tf32.tf32.f32 "
        "{%0,%1,%2,%3}, {%4,%5,%6,%7}, {%8,%9}, {%0,%1,%2,%3};"
        : "+f"(c0), "+f"(c1), "+f"(c2), "+f"(c3)
        : "r"(a0), "r"(a1), "r"(a2), "r"(a3), "r"(b0), "r"(b1));
}

// ---------------------------------------------------------------------------
// TF32 mma.sync GEMM: C[M,N] = A[M,K] @ B[N,K]^T  (row-major, K contiguous)
// (unchanged from R4 — verified)
// ---------------------------------------------------------------------------
#define TM  128
#define TN  128
#define BKF 32
#define SSTR 36

__global__ __launch_bounds__(256, 2) void gemm_tf32_nt(
    const float* __restrict__ A, const float* __restrict__ B,
    float* __restrict__ C, int M, int N, int K)
{
    __shared__ float As[TM][SSTR];
    __shared__ float Bs[TN][SSTR];

    const int tid  = threadIdx.x;
    const int wid  = tid >> 5;
    const int lane = tid & 31;
    const int g = lane >> 2;
    const int t = lane & 3;
    const int wm = (wid & 3) * 32;
    const int wn = (wid >> 2) * 64;
    const int m0 = blockIdx.y * TM;
    const int n0 = blockIdx.x * TN;

    float c[2][8][4];
#pragma unroll
    for (int mi = 0; mi < 2; mi++)
#pragma unroll
        for (int ni = 0; ni < 8; ni++)
#pragma unroll
            for (int r = 0; r < 4; r++) c[mi][ni][r] = 0.0f;

    for (int k0 = 0; k0 < K; k0 += BKF) {
#pragma unroll
        for (int i = 0; i < 4; i++) {
            int e   = tid + i * 256;
            int row = e >> 3;
            int q   = (e & 7) * 4;
            float4 va = *(const float4*)(A + (size_t)(m0 + row) * K + k0 + q);
            float4 vb = *(const float4*)(B + (size_t)(n0 + row) * K + k0 + q);
            *(uint4*)&As[row][q] = make_uint4(f2tf32(va.x), f2tf32(va.y),
                                              f2tf32(va.z), f2tf32(va.w));
            *(uint4*)&Bs[row][q] = make_uint4(f2tf32(vb.x), f2tf32(vb.y),
                                              f2tf32(vb.z), f2tf32(vb.w));
        }
        __syncthreads();

#pragma unroll
        for (int kk = 0; kk < 4; kk++) {
            const int kb = kk * 8;
            uint32_t a[2][4];
#pragma unroll
            for (int mi = 0; mi < 2; mi++) {
                const float* ar0 = &As[wm + mi * 16 + g][kb + t];
                const float* ar1 = &As[wm + mi * 16 + g + 8][kb + t];
                a[mi][0] = __float_as_uint(ar0[0]);
                a[mi][1] = __float_as_uint(ar1[0]);
                a[mi][2] = __float_as_uint(ar0[4]);
                a[mi][3] = __float_as_uint(ar1[4]);
            }
            uint32_t b[8][2];
#pragma unroll
            for (int ni = 0; ni < 8; ni++) {
                const float* br = &Bs[wn + ni * 8 + g][kb + t];
                b[ni][0] = __float_as_uint(br[0]);
                b[ni][1] = __float_as_uint(br[4]);
            }
#pragma unroll
            for (int mi = 0; mi < 2; mi++)
#pragma unroll
                for (int ni = 0; ni < 8; ni++)
                    mma_tf32(c[mi][ni][0], c[mi][ni][1], c[mi][ni][2], c[mi][ni][3],
                             a[mi][0], a[mi][1], a[mi][2], a[mi][3],
                             b[ni][0], b[ni][1]);
        }
        __syncthreads();
    }

#pragma unroll
    for (int mi = 0; mi < 2; mi++) {
        const int row = m0 + wm + mi * 16 + g;
#pragma unroll
        for (int ni = 0; ni < 8; ni++) {
            const int col = n0 + wn + ni * 8 + 2 * t;
            *(float2*)(C + (size_t)row * N + col) =
                make_float2(c[mi][ni][0], c[mi][ni][1]);
            *(float2*)(C + (size_t)(row + 8) * N + col) =
                make_float2(c[mi][ni][2], c[mi][ni][3]);
        }
    }
}

// ---------------------------------------------------------------------------
// RoPE in-place on q and k thirds of g_qkv.
// ---------------------------------------------------------------------------
__global__ __launch_bounds__(256) void rope_kernel(
    float* __restrict__ qkv, const float* __restrict__ cs,
    const float* __restrict__ sn)
{
    const int total = BT * HEADS * (HD / 2);
    for (int idx = blockIdx.x * blockDim.x + threadIdx.x; idx < total;
         idx += gridDim.x * blockDim.x) {
        int i   = idx & 31;
        int h   = (idx >> 5) & 15;
        int row = idx >> 9;
        int t   = row & (TSEQ - 1);
        float c = cs[t * 32 + i];
        float s = sn[t * 32 + i];
        float* q = qkv + (size_t)row * QKVDIM + h * HD + 2 * i;
        float2 qv = *(float2*)q;
        *(float2*)q = make_float2(qv.x * c - qv.y * s, qv.x * s + qv.y * c);
        float* k = q + CDIM;
        float2 kv = *(float2*)k;
        *(float2*)k = make_float2(kv.x * c - kv.y * s, kv.x * s + kv.y * c);
    }
}

// ---------------------------------------------------------------------------
// Flash attention with tf32 mma.sync.
// CTA: 128 Q rows x one (b,h). 8 warps; warp w owns rows w*16..w*16+15.
// Key tiles of 64. Q fragments register-resident (scale folded in).
// P staged per-warp in smem (warp-private region -> __syncwarp only).
// ---------------------------------------------------------------------------
#define AM 128
#define AN 64
#define ASTR 68

__global__ __launch_bounds__(256, 1) void attn_mma(
    const float* __restrict__ qkv, float* __restrict__ ao)
{
    extern __shared__ float sm[];
    float* Ks = sm;                     // [64][68] tf32 bits
    float* Vs = Ks + AN * ASTR;         // [64][68] tf32 bits
    float* Pb = Vs + AN * ASTR;         // [128][68] Q staging, then P staging

    const int m0 = blockIdx.x * AM;
    const int h  = blockIdx.y;
    const int b  = blockIdx.z;
    const int tid = threadIdx.x;
    const int wid = tid >> 5, lane = tid & 31;
    const int g = lane >> 2, t = lane & 3;
    const int wrow = wid * 16;

    // ---- Stage Q (scaled, tf32) into Pb, then read register fragments ----
    const float* qbase = qkv + ((size_t)(b * TSEQ + m0)) * QKVDIM + h * HD;
    for (int e = tid; e < AM * 16; e += 256) {
        int r = e >> 4, c4 = (e & 15) * 4;
        float4 v = *(const float4*)(qbase + (size_t)r * QKVDIM + c4);
        *(uint4*)(Pb + r * ASTR + c4) = make_uint4(
            f2tf32(v.x * 0.125f), f2tf32(v.y * 0.125f),
            f2tf32(v.z * 0.125f), f2tf32(v.w * 0.125f));
    }
    __syncthreads();
    uint32_t qa[8][4];
#pragma unroll
    for (int kd = 0; kd < 8; kd++) {
        qa[kd][0] = __float_as_uint(Pb[(wrow + g) * ASTR + kd * 8 + t]);
        qa[kd][1] = __float_as_uint(Pb[(wrow + g + 8) * ASTR + kd * 8 + t]);
        qa[kd][2] = __float_as_uint(Pb[(wrow + g) * ASTR + kd * 8 + t + 4]);
        qa[kd][3] = __float_as_uint(Pb[(wrow + g + 8) * ASTR + kd * 8 + t + 4]);
    }
    // Pb reuse below is warp-private; no block barrier needed here.

    float o[8][4];
#pragma unroll
    for (int nj = 0; nj < 8; nj++)
#pragma unroll
        for (int r = 0; r < 4; r++) o[nj][r] = 0.0f;
    float mx0 = -1e30f, mx1 = -1e30f, l0 = 0.0f, l1 = 0.0f;

    const int ntiles = (m0 + AM) / AN;
    for (int kt = 0; kt < ntiles; kt++) {
        const int n0 = kt * AN;
        __syncthreads();   // protect Ks/Vs (and initial Pb staging on kt=0)
        const float* kb = qkv + ((size_t)(b * TSEQ + n0)) * QKVDIM + CDIM + h * HD;
        const float* vb = kb + CDIM;
        for (int e = tid; e < AN * 16; e += 256) {
            int r = e >> 4, c4 = (e & 15) * 4;
            float4 kv4 = *(const float4*)(kb + (size_t)r * QKVDIM + c4);
            float4 vv4 = *(const float4*)(vb + (size_t)r * QKVDIM + c4);
            *(uint4*)(Ks + r * ASTR + c4) = make_uint4(
                f2tf32(kv4.x), f2tf32(kv4.y), f2tf32(kv4.z), f2tf32(kv4.w));
            *(uint4*)(Vs + r * ASTR + c4) = make_uint4(
                f2tf32(vv4.x), f2tf32(vv4.y), f2tf32(vv4.z), f2tf32(vv4.w));
        }
        __syncthreads();

        // ---- S = Q K^T ----
        float s[8][4];
#pragma unroll
        for (int nj = 0; nj < 8; nj++)
#pragma unroll
            for (int r = 0; r < 4; r++) s[nj][r] = 0.0f;
#pragma unroll
        for (int kd = 0; kd < 8; kd++) {
#pragma unroll
            for (int nj = 0; nj < 8; nj++) {
                uint32_t b0 = __float_as_uint(Ks[(nj * 8 + g) * ASTR + kd * 8 + t]);
                uint32_t b1 = __float_as_uint(Ks[(nj * 8 + g) * ASTR + kd * 8 + t + 4]);
                mma_tf32(s[nj][0], s[nj][1], s[nj][2], s[nj][3],
                         qa[kd][0], qa[kd][1], qa[kd][2], qa[kd][3], b0, b1);
            }
        }

        // ---- causal mask (only when tile overlaps/exceeds warp rows) ----
        const int row0 = m0 + wrow + g;
        const int row1 = row0 + 8;
        if (n0 + AN - 1 > m0 + wrow) {
#pragma unroll
            for (int nj = 0; nj < 8; nj++) {
                int col = n0 + nj * 8 + 2 * t;
                if (col     > row0) s[nj][0] = -1e30f;
                if (col + 1 > row0) s[nj][1] = -1e30f;
                if (col     > row1) s[nj][2] = -1e30f;
                if (col + 1 > row1) s[nj][3] = -1e30f;
            }
        }

        // ---- online softmax (2 rows per thread) ----
        float rm0 = -1e30f, rm1 = -1e30f;
#pragma unroll
        for (int nj = 0; nj < 8; nj++) {
            rm0 = fmaxf(rm0, fmaxf(s[nj][0], s[nj][1]));
            rm1 = fmaxf(rm1, fmaxf(s[nj][2], s[nj][3]));
        }
        rm0 = fmaxf(rm0, __shfl_xor_sync(0xffffffffu, rm0, 1));
        rm0 = fmaxf(rm0, __shfl_xor_sync(0xffffffffu, rm0, 2));
        rm1 = fmaxf(rm1, __shfl_xor_sync(0xffffffffu, rm1, 1));
        rm1 = fmaxf(rm1, __shfl_xor_sync(0xffffffffu, rm1, 2));
        float nm0 = fmaxf(mx0, rm0), nm1 = fmaxf(mx1, rm1);
        float al0 = __expf(mx0 - nm0), al1 = __expf(mx1 - nm1);
        mx0 = nm0; mx1 = nm1;

        float rs0 = 0.0f, rs1 = 0.0f;
#pragma unroll
        for (int nj = 0; nj < 8; nj++) {
            float p0 = __expf(s[nj][0] - nm0);
            float p1 = __expf(s[nj][1] - nm0);
            float p2 = __expf(s[nj][2] - nm1);
            float p3 = __expf(s[nj][3] - nm1);
            rs0 += p0 + p1; rs1 += p2 + p3;
            *(uint2*)(Pb + (wrow + g) * ASTR + nj * 8 + 2 * t) =
                make_uint2(f2tf32(p0), f2tf32(p1));
            *(uint2*)(Pb + (wrow + g + 8) * ASTR + nj * 8 + 2 * t) =
                make_uint2(f2tf32(p2), f2tf32(p3));
        }
        rs0 += __shfl_xor_sync(0xffffffffu, rs0, 1);
        rs0 += __shfl_xor_sync(0xffffffffu, rs0, 2);
        rs1 += __shfl_xor_sync(0xffffffffu, rs1, 1);
        rs1 += __shfl_xor_sync(0xffffffffu, rs1, 2);
        l0 = l0 * al0 + rs0;
        l1 = l1 * al1 + rs1;
#pragma unroll
        for (int nj = 0; nj < 8; nj++) {
            o[nj][0] *= al0; o[nj][1] *= al0;
            o[nj][2] *= al1; o[nj][3] *= al1;
        }
        __syncwarp();

        // ---- O += P V ----
#pragma unroll
        for (int kp = 0; kp < 8; kp++) {
            uint32_t pa0 = __float_as_uint(Pb[(wrow + g) * ASTR + kp * 8 + t]);
            uint32_t pa1 = __float_as_uint(Pb[(wrow + g + 8) * ASTR + kp * 8 + t]);
            uint32_t pa2 = __float_as_uint(Pb[(wrow + g) * ASTR + kp * 8 + t + 4]);
            uint32_t pa3 = __float_as_uint(Pb[(wrow + g + 8) * ASTR + kp * 8 + t + 4]);
#pragma unroll
            for (int nj = 0; nj < 8; nj++) {
                uint32_t b0 = __float_as_uint(Vs[(kp * 8 + t) * ASTR + nj * 8 + g]);
                uint32_t b1 = __float_as_uint(Vs[(kp * 8 + t + 4) * ASTR + nj * 8 + g]);
                mma_tf32(o[nj][0], o[nj][1], o[nj][2], o[nj][3],
                         pa0, pa1, pa2, pa3, b0, b1);
            }
        }
        __syncwarp();   // P loads done before next iteration's P stores
    }

    // ---- normalize + write ----
    const float i0 = 1.0f / l0, i1 = 1.0f / l1;
    const int row0 = m0 + wrow + g;
    float* ob0 = ao + ((size_t)(b * TSEQ + row0)) * CDIM + h * HD;
    float* ob1 = ob0 + 8 * CDIM;
#pragma unroll
    for (int nj = 0; nj < 8; nj++) {
        *(float2*)(ob0 + nj * 8 + 2 * t) = make_float2(o[nj][0] * i0, o[nj][1] * i0);
        *(float2*)(ob1 + nj * 8 + 2 * t) = make_float2(o[nj][2] * i1, o[nj][3] * i1);
    }
}

// ---------------------------------------------------------------------------
// Host launcher
// ---------------------------------------------------------------------------
extern "C" void kernel_launch(void* const* d_in, const int* in_sizes, int n_in,
                              void* d_out, int out_size)
{
    const float* x       = (const float*)d_in[0];  // [2,2048,1024]
    const float* f_cos   = (const float*)d_in[1];  // [2048,32]
    const float* f_sin   = (const float*)d_in[2];  // [2048,32]
    const float* qkv_w   = (const float*)d_in[3];  // [3072,1024]
    const float* proj_w  = (const float*)d_in[4];  // [1024,1024]
    float* out = (float*)d_out;

    float *qkv_ptr, *ao_ptr;
    cudaGetSymbolAddress((void**)&qkv_ptr, g_qkv);
    cudaGetSymbolAddress((void**)&ao_ptr, g_ao);

    // 1) QKV projection (tf32 mma.sync)
    {
        dim3 grid(QKVDIM / TN, BT / TM);
        gemm_tf32_nt<<<grid, 256>>>(x, qkv_w, qkv_ptr, BT, QKVDIM, CDIM);
    }

    // 2) RoPE
    rope_kernel<<<2048, 256>>>(qkv_ptr, f_cos, f_sin);

    // 3) Causal flash attention (tf32 mma.sync)
    {
        const int smem = (2 * AN * ASTR + AM * ASTR) * (int)sizeof(float); // 69632
        cudaFuncSetAttribute(attn_mma,
                             cudaFuncAttributeMaxDynamicSharedMemorySize, smem);
        dim3 grid(TSEQ / AM, HEADS, BATCH);
        attn_mma<<<grid, 256, smem>>>(qkv_ptr, ao_ptr);
    }

    // 4) Output projection (tf32 mma.sync)
    {
        dim3 grid(CDIM / TN, BT / TM);
        gemm_tf32_nt<<<grid, 256>>>(ao_ptr, proj_w, out, BT, CDIM, CDIM);
    }
}

// round 9
// speedup vs baseline: 3.7575x; 1.1292x over previous
#include <cuda_runtime.h>
#include <cstdint>
#include <math.h>

// Problem constants
#define BATCH   2
#define TSEQ    2048
#define CDIM    1024
#define HEADS   16
#define HD      64
#define BT      (BATCH * TSEQ)          // 4096 rows
#define QKVDIM  (3 * CDIM)              // 3072

// Scratch (allocation-free rule: __device__ globals)
__device__ float g_qkv[(size_t)BT * QKVDIM];   // [4096, 3072]
__device__ float g_ao [(size_t)BT * CDIM];     // [4096, 1024]

__device__ __forceinline__ uint32_t f2tf32(float v) {
    uint32_t u;
    asm("cvt.rna.tf32.f32 %0, %1;" : "=r"(u) : "f"(v));
    return u;
}
__device__ __forceinline__ uint32_t smem_u32(const void* p) {
    uint32_t a;
    asm("{ .reg .u64 t; cvta.to.shared.u64 t, %1; cvt.u32.u64 %0, t; }"
        : "=r"(a) : "l"(p));
    return a;
}
__device__ __forceinline__ void cp_async16(uint32_t dst, const void* src) {
    asm volatile("cp.async.cg.shared.global [%0], [%1], 16;"
                 :: "r"(dst), "l"(src));
}

__device__ __forceinline__ void mma_tf32(
    float& c0, float& c1, float& c2, float& c3,
    uint32_t a0, uint32_t a1, uint32_t a2, uint32_t a3,
    uint32_t b0, uint32_t b1)
{
    asm volatile(
        "mma.sync.aligned.m16n8k8.row.col.f32.tf32.tf32.f32 "
        "{%0,%1,%2,%3}, {%4,%5,%6,%7}, {%8,%9}, {%0,%1,%2,%3};"
        : "+f"(c0), "+f"(c1), "+f"(c2), "+f"(c3)
        : "r"(a0), "r"(a1), "r"(a2), "r"(a3), "r"(b0), "r"(b1));
}

// ---------------------------------------------------------------------------
// TF32 mma.sync GEMM with 2-stage cp.async pipeline.
// C[M,N] = A[M,K] @ B[N,K]^T. 128x128 CTA tile, BK=32, 8 warps (4Mx2N),
// warp tile 32x64. Raw fp32 staged via cp.async; cvt.rna at fragment read.
// ---------------------------------------------------------------------------
#define TM  128
#define TN  128
#define BKF 32
#define SSTR 36
#define STG (TM * SSTR)            // floats per matrix per stage (4608)
#define GEMM_SMEM (2 * 2 * STG * 4)  // 73728 bytes

__global__ __launch_bounds__(256, 2) void gemm_tf32_nt(
    const float* __restrict__ A, const float* __restrict__ B,
    float* __restrict__ C, int M, int N, int K)
{
    extern __shared__ __align__(16) float smf[];

    const int tid  = threadIdx.x;
    const int wid  = tid >> 5;
    const int lane = tid & 31;
    const int g = lane >> 2;
    const int t = lane & 3;
    const int wm = (wid & 3) * 32;
    const int wn = (wid >> 2) * 64;
    const int m0 = blockIdx.y * TM;
    const int n0 = blockIdx.x * TN;

    const int lrow = tid >> 3;            // 0..31 (row group per 4 iters)
    const int lq   = (tid & 7) * 4;       // float offset in row

    float c[2][8][4];
#pragma unroll
    for (int mi = 0; mi < 2; mi++)
#pragma unroll
        for (int ni = 0; ni < 8; ni++)
#pragma unroll
            for (int r = 0; r < 4; r++) c[mi][ni][r] = 0.0f;

    const int nch = K / BKF;

    // Issue loads for stage s covering k-chunk k0.
    auto issue_load = [&](int s, int k0) {
        float* As = smf + s * 2 * STG;
        float* Bs = As + STG;
#pragma unroll
        for (int i = 0; i < 4; i++) {
            int row = lrow + i * 32;
            uint32_t da = smem_u32(As + row * SSTR + lq);
            uint32_t db = smem_u32(Bs + row * SSTR + lq);
            cp_async16(da, A + (size_t)(m0 + row) * K + k0 + lq);
            cp_async16(db, B + (size_t)(n0 + row) * K + k0 + lq);
        }
    };

    issue_load(0, 0);
    asm volatile("cp.async.commit_group;");

    for (int cch = 0; cch < nch; cch++) {
        if (cch + 1 < nch) issue_load((cch + 1) & 1, (cch + 1) * BKF);
        asm volatile("cp.async.commit_group;");
        asm volatile("cp.async.wait_group 1;");
        __syncthreads();

        const float* As = smf + (cch & 1) * 2 * STG;
        const float* Bs = As + STG;

#pragma unroll
        for (int kk = 0; kk < 4; kk++) {
            const int kb = kk * 8;
            uint32_t a[2][4];
#pragma unroll
            for (int mi = 0; mi < 2; mi++) {
                const float* ar0 = &As[(wm + mi * 16 + g) * SSTR + kb + t];
                const float* ar1 = &As[(wm + mi * 16 + g + 8) * SSTR + kb + t];
                a[mi][0] = f2tf32(ar0[0]);
                a[mi][1] = f2tf32(ar1[0]);
                a[mi][2] = f2tf32(ar0[4]);
                a[mi][3] = f2tf32(ar1[4]);
            }
            uint32_t b[8][2];
#pragma unroll
            for (int ni = 0; ni < 8; ni++) {
                const float* br = &Bs[(wn + ni * 8 + g) * SSTR + kb + t];
                b[ni][0] = f2tf32(br[0]);
                b[ni][1] = f2tf32(br[4]);
            }
#pragma unroll
            for (int mi = 0; mi < 2; mi++)
#pragma unroll
                for (int ni = 0; ni < 8; ni++)
                    mma_tf32(c[mi][ni][0], c[mi][ni][1], c[mi][ni][2], c[mi][ni][3],
                             a[mi][0], a[mi][1], a[mi][2], a[mi][3],
                             b[ni][0], b[ni][1]);
        }
        __syncthreads();   // all reads of this stage done before it is reloaded
    }

#pragma unroll
    for (int mi = 0; mi < 2; mi++) {
        const int row = m0 + wm + mi * 16 + g;
#pragma unroll
        for (int ni = 0; ni < 8; ni++) {
            const int col = n0 + wn + ni * 8 + 2 * t;
            *(float2*)(C + (size_t)row * N + col) =
                make_float2(c[mi][ni][0], c[mi][ni][1]);
            *(float2*)(C + (size_t)(row + 8) * N + col) =
                make_float2(c[mi][ni][2], c[mi][ni][3]);
        }
    }
}

// ---------------------------------------------------------------------------
// RoPE in-place on q and k thirds of g_qkv.
// ---------------------------------------------------------------------------
__global__ __launch_bounds__(256) void rope_kernel(
    float* __restrict__ qkv, const float* __restrict__ cs,
    const float* __restrict__ sn)
{
    const int total = BT * HEADS * (HD / 2);
    for (int idx = blockIdx.x * blockDim.x + threadIdx.x; idx < total;
         idx += gridDim.x * blockDim.x) {
        int i   = idx & 31;
        int h   = (idx >> 5) & 15;
        int row = idx >> 9;
        int t   = row & (TSEQ - 1);
        float c = cs[t * 32 + i];
        float s = sn[t * 32 + i];
        float* q = qkv + (size_t)row * QKVDIM + h * HD + 2 * i;
        float2 qv = *(float2*)q;
        *(float2*)q = make_float2(qv.x * c - qv.y * s, qv.x * s + qv.y * c);
        float* k = q + CDIM;
        float2 kv = *(float2*)k;
        *(float2*)k = make_float2(kv.x * c - kv.y * s, kv.x * s + kv.y * c);
    }
}

// ---------------------------------------------------------------------------
// Flash attention with tf32 mma.sync. (verified R6 structure)
// Changes: occupancy 2, reversed tile order for long-first scheduling.
// ---------------------------------------------------------------------------
#define AM 128
#define AN 64
#define ASTR 68

__global__ __launch_bounds__(256, 2) void attn_mma(
    const float* __restrict__ qkv, float* __restrict__ ao)
{
    extern __shared__ float sm[];
    float* Ks = sm;                     // [64][68] tf32 bits
    float* Vs = Ks + AN * ASTR;         // [64][68] tf32 bits
    float* Pb = Vs + AN * ASTR;         // [128][68] Q staging, then P staging

    // Long-first: block 0 takes the LAST (longest-KV) tile.
    const int m0 = (gridDim.x - 1 - blockIdx.x) * AM;
    const int h  = blockIdx.y;
    const int b  = blockIdx.z;
    const int tid = threadIdx.x;
    const int wid = tid >> 5, lane = tid & 31;
    const int g = lane >> 2, t = lane & 3;
    const int wrow = wid * 16;

    // ---- Stage Q (scaled, tf32) into Pb, then read register fragments ----
    const float* qbase = qkv + ((size_t)(b * TSEQ + m0)) * QKVDIM + h * HD;
    for (int e = tid; e < AM * 16; e += 256) {
        int r = e >> 4, c4 = (e & 15) * 4;
        float4 v = *(const float4*)(qbase + (size_t)r * QKVDIM + c4);
        *(uint4*)(Pb + r * ASTR + c4) = make_uint4(
            f2tf32(v.x * 0.125f), f2tf32(v.y * 0.125f),
            f2tf32(v.z * 0.125f), f2tf32(v.w * 0.125f));
    }
    __syncthreads();
    uint32_t qa[8][4];
#pragma unroll
    for (int kd = 0; kd < 8; kd++) {
        qa[kd][0] = __float_as_uint(Pb[(wrow + g) * ASTR + kd * 8 + t]);
        qa[kd][1] = __float_as_uint(Pb[(wrow + g + 8) * ASTR + kd * 8 + t]);
        qa[kd][2] = __float_as_uint(Pb[(wrow + g) * ASTR + kd * 8 + t + 4]);
        qa[kd][3] = __float_as_uint(Pb[(wrow + g + 8) * ASTR + kd * 8 + t + 4]);
    }

    float o[8][4];
#pragma unroll
    for (int nj = 0; nj < 8; nj++)
#pragma unroll
        for (int r = 0; r < 4; r++) o[nj][r] = 0.0f;
    float mx0 = -1e30f, mx1 = -1e30f, l0 = 0.0f, l1 = 0.0f;

    const int ntiles = (m0 + AM) / AN;
    for (int kt = 0; kt < ntiles; kt++) {
        const int n0 = kt * AN;
        __syncthreads();   // protect Ks/Vs (and initial Pb staging on kt=0)
        const float* kb = qkv + ((size_t)(b * TSEQ + n0)) * QKVDIM + CDIM + h * HD;
        const float* vb = kb + CDIM;
        for (int e = tid; e < AN * 16; e += 256) {
            int r = e >> 4, c4 = (e & 15) * 4;
            float4 kv4 = *(const float4*)(kb + (size_t)r * QKVDIM + c4);
            float4 vv4 = *(const float4*)(vb + (size_t)r * QKVDIM + c4);
            *(uint4*)(Ks + r * ASTR + c4) = make_uint4(
                f2tf32(kv4.x), f2tf32(kv4.y), f2tf32(kv4.z), f2tf32(kv4.w));
            *(uint4*)(Vs + r * ASTR + c4) = make_uint4(
                f2tf32(vv4.x), f2tf32(vv4.y), f2tf32(vv4.z), f2tf32(vv4.w));
        }
        __syncthreads();

        // ---- S = Q K^T ----
        float s[8][4];
#pragma unroll
        for (int nj = 0; nj < 8; nj++)
#pragma unroll
            for (int r = 0; r < 4; r++) s[nj][r] = 0.0f;
#pragma unroll
        for (int kd = 0; kd < 8; kd++) {
#pragma unroll
            for (int nj = 0; nj < 8; nj++) {
                uint32_t b0 = __float_as_uint(Ks[(nj * 8 + g) * ASTR + kd * 8 + t]);
                uint32_t b1 = __float_as_uint(Ks[(nj * 8 + g) * ASTR + kd * 8 + t + 4]);
                mma_tf32(s[nj][0], s[nj][1], s[nj][2], s[nj][3],
                         qa[kd][0], qa[kd][1], qa[kd][2], qa[kd][3], b0, b1);
            }
        }

        // ---- causal mask ----
        const int row0 = m0 + wrow + g;
        const int row1 = row0 + 8;
        if (n0 + AN - 1 > m0 + wrow) {
#pragma unroll
            for (int nj = 0; nj < 8; nj++) {
                int col = n0 + nj * 8 + 2 * t;
                if (col     > row0) s[nj][0] = -1e30f;
                if (col + 1 > row0) s[nj][1] = -1e30f;
                if (col     > row1) s[nj][2] = -1e30f;
                if (col + 1 > row1) s[nj][3] = -1e30f;
            }
        }

        // ---- online softmax (2 rows per thread) ----
        float rm0 = -1e30f, rm1 = -1e30f;
#pragma unroll
        for (int nj = 0; nj < 8; nj++) {
            rm0 = fmaxf(rm0, fmaxf(s[nj][0], s[nj][1]));
            rm1 = fmaxf(rm1, fmaxf(s[nj][2], s[nj][3]));
        }
        rm0 = fmaxf(rm0, __shfl_xor_sync(0xffffffffu, rm0, 1));
        rm0 = fmaxf(rm0, __shfl_xor_sync(0xffffffffu, rm0, 2));
        rm1 = fmaxf(rm1, __shfl_xor_sync(0xffffffffu, rm1, 1));
        rm1 = fmaxf(rm1, __shfl_xor_sync(0xffffffffu, rm1, 2));
        float nm0 = fmaxf(mx0, rm0), nm1 = fmaxf(mx1, rm1);
        float al0 = __expf(mx0 - nm0), al1 = __expf(mx1 - nm1);
        mx0 = nm0; mx1 = nm1;

        float rs0 = 0.0f, rs1 = 0.0f;
#pragma unroll
        for (int nj = 0; nj < 8; nj++) {
            float p0 = __expf(s[nj][0] - nm0);
            float p1 = __expf(s[nj][1] - nm0);
            float p2 = __expf(s[nj][2] - nm1);
            float p3 = __expf(s[nj][3] - nm1);
            rs0 += p0 + p1; rs1 += p2 + p3;
            *(uint2*)(Pb + (wrow + g) * ASTR + nj * 8 + 2 * t) =
                make_uint2(f2tf32(p0), f2tf32(p1));
            *(uint2*)(Pb + (wrow + g + 8) * ASTR + nj * 8 + 2 * t) =
                make_uint2(f2tf32(p2), f2tf32(p3));
        }
        rs0 += __shfl_xor_sync(0xffffffffu, rs0, 1);
        rs0 += __shfl_xor_sync(0xffffffffu, rs0, 2);
        rs1 += __shfl_xor_sync(0xffffffffu, rs1, 1);
        rs1 += __shfl_xor_sync(0xffffffffu, rs1, 2);
        l0 = l0 * al0 + rs0;
        l1 = l1 * al1 + rs1;
#pragma unroll
        for (int nj = 0; nj < 8; nj++) {
            o[nj][0] *= al0; o[nj][1] *= al0;
            o[nj][2] *= al1; o[nj][3] *= al1;
        }
        __syncwarp();

        // ---- O += P V ----
#pragma unroll
        for (int kp = 0; kp < 8; kp++) {
            uint32_t pa0 = __float_as_uint(Pb[(wrow + g) * ASTR + kp * 8 + t]);
            uint32_t pa1 = __float_as_uint(Pb[(wrow + g + 8) * ASTR + kp * 8 + t]);
            uint32_t pa2 = __float_as_uint(Pb[(wrow + g) * ASTR + kp * 8 + t + 4]);
            uint32_t pa3 = __float_as_uint(Pb[(wrow + g + 8) * ASTR + kp * 8 + t + 4]);
#pragma unroll
            for (int nj = 0; nj < 8; nj++) {
                uint32_t b0 = __float_as_uint(Vs[(kp * 8 + t) * ASTR + nj * 8 + g]);
                uint32_t b1 = __float_as_uint(Vs[(kp * 8 + t + 4) * ASTR + nj * 8 + g]);
                mma_tf32(o[nj][0], o[nj][1], o[nj][2], o[nj][3],
                         pa0, pa1, pa2, pa3, b0, b1);
            }
        }
        __syncwarp();   // P loads done before next iteration's P stores
    }

    // ---- normalize + write ----
    const float i0 = 1.0f / l0, i1 = 1.0f / l1;
    const int row0 = m0 + wrow + g;
    float* ob0 = ao + ((size_t)(b * TSEQ + row0)) * CDIM + h * HD;
    float* ob1 = ob0 + 8 * CDIM;
#pragma unroll
    for (int nj = 0; nj < 8; nj++) {
        *(float2*)(ob0 + nj * 8 + 2 * t) = make_float2(o[nj][0] * i0, o[nj][1] * i0);
        *(float2*)(ob1 + nj * 8 + 2 * t) = make_float2(o[nj][2] * i1, o[nj][3] * i1);
    }
}

// ---------------------------------------------------------------------------
// Host launcher
// ---------------------------------------------------------------------------
extern "C" void kernel_launch(void* const* d_in, const int* in_sizes, int n_in,
                              void* d_out, int out_size)
{
    const float* x       = (const float*)d_in[0];  // [2,2048,1024]
    const float* f_cos   = (const float*)d_in[1];  // [2048,32]
    const float* f_sin   = (const float*)d_in[2];  // [2048,32]
    const float* qkv_w   = (const float*)d_in[3];  // [3072,1024]
    const float* proj_w  = (const float*)d_in[4];  // [1024,1024]
    float* out = (float*)d_out;

    float *qkv_ptr, *ao_ptr;
    cudaGetSymbolAddress((void**)&qkv_ptr, g_qkv);
    cudaGetSymbolAddress((void**)&ao_ptr, g_ao);

    cudaFuncSetAttribute(gemm_tf32_nt,
                         cudaFuncAttributeMaxDynamicSharedMemorySize, GEMM_SMEM);

    // 1) QKV projection (tf32 mma.sync, cp.async pipelined)
    {
        dim3 grid(QKVDIM / TN, BT / TM);
        gemm_tf32_nt<<<grid, 256, GEMM_SMEM>>>(x, qkv_w, qkv_ptr, BT, QKVDIM, CDIM);
    }

    // 2) RoPE
    rope_kernel<<<2048, 256>>>(qkv_ptr, f_cos, f_sin);

    // 3) Causal flash attention (tf32 mma.sync)
    {
        const int smem = (2 * AN * ASTR + AM * ASTR) * (int)sizeof(float); // 69632
        cudaFuncSetAttribute(attn_mma,
                             cudaFuncAttributeMaxDynamicSharedMemorySize, smem);
        dim3 grid(TSEQ / AM, HEADS, BATCH);
        attn_mma<<<grid, 256, smem>>>(qkv_ptr, ao_ptr);
    }

    // 4) Output projection (tf32 mma.sync, cp.async pipelined)
    {
        dim3 grid(CDIM / TN, BT / TM);
        gemm_tf32_nt<<<grid, 256, GEMM_SMEM>>>(ao_ptr, proj_w, out, BT, CDIM, CDIM);
    }
}

// round 10
// speedup vs baseline: 3.8292x; 1.0191x over previous
#include <cuda_runtime.h>
#include <cstdint>
#include <math.h>

// Problem constants
#define BATCH   2
#define TSEQ    2048
#define CDIM    1024
#define HEADS   16
#define HD      64
#define BT      (BATCH * TSEQ)          // 4096 rows
#define QKVDIM  (3 * CDIM)              // 3072

// Scratch (allocation-free rule: __device__ globals)
__device__ float g_qkv[(size_t)BT * QKVDIM];   // [4096, 3072]
__device__ float g_ao [(size_t)BT * CDIM];     // [4096, 1024]

__device__ __forceinline__ uint32_t f2tf32(float v) {
    uint32_t u;
    asm("cvt.rna.tf32.f32 %0, %1;" : "=r"(u) : "f"(v));
    return u;
}
__device__ __forceinline__ uint32_t smem_u32(const void* p) {
    uint32_t a;
    asm("{ .reg .u64 t; cvta.to.shared.u64 t, %1; cvt.u32.u64 %0, t; }"
        : "=r"(a) : "l"(p));
    return a;
}
__device__ __forceinline__ void cp_async16(uint32_t dst, const void* src) {
    asm volatile("cp.async.cg.shared.global [%0], [%1], 16;"
                 :: "r"(dst), "l"(src));
}

__device__ __forceinline__ void mma_tf32(
    float& c0, float& c1, float& c2, float& c3,
    uint32_t a0, uint32_t a1, uint32_t a2, uint32_t a3,
    uint32_t b0, uint32_t b1)
{
    asm volatile(
        "mma.sync.aligned.m16n8k8.row.col.f32.tf32.tf32.f32 "
        "{%0,%1,%2,%3}, {%4,%5,%6,%7}, {%8,%9}, {%0,%1,%2,%3};"
        : "+f"(c0), "+f"(c1), "+f"(c2), "+f"(c3)
        : "r"(a0), "r"(a1), "r"(a2), "r"(a3), "r"(b0), "r"(b1));
}

// ---------------------------------------------------------------------------
// TF32 mma.sync GEMM with 2-stage cp.async pipeline, one barrier/chunk.
// C[M,N] = A[M,K] @ B[N,K]^T. 128x128 CTA tile, BK=32, 8 warps (4Mx2N).
// ---------------------------------------------------------------------------
#define TM  128
#define TN  128
#define BKF 32
#define SSTR 36
#define STG (TM * SSTR)              // floats per matrix per stage (4608)
#define GEMM_SMEM (2 * 2 * STG * 4)  // 73728 bytes

__global__ __launch_bounds__(256, 2) void gemm_tf32_nt(
    const float* __restrict__ A, const float* __restrict__ B,
    float* __restrict__ C, int M, int N, int K)
{
    extern __shared__ __align__(16) float smf[];

    const int tid  = threadIdx.x;
    const int wid  = tid >> 5;
    const int lane = tid & 31;
    const int g = lane >> 2;
    const int t = lane & 3;
    const int wm = (wid & 3) * 32;
    const int wn = (wid >> 2) * 64;
    const int m0 = blockIdx.y * TM;
    const int n0 = blockIdx.x * TN;

    const int lrow = tid >> 3;
    const int lq   = (tid & 7) * 4;

    float c[2][8][4];
#pragma unroll
    for (int mi = 0; mi < 2; mi++)
#pragma unroll
        for (int ni = 0; ni < 8; ni++)
#pragma unroll
            for (int r = 0; r < 4; r++) c[mi][ni][r] = 0.0f;

    const int nch = K / BKF;

    auto issue_load = [&](int s, int k0) {
        float* As = smf + s * 2 * STG;
        float* Bs = As + STG;
#pragma unroll
        for (int i = 0; i < 4; i++) {
            int row = lrow + i * 32;
            cp_async16(smem_u32(As + row * SSTR + lq),
                       A + (size_t)(m0 + row) * K + k0 + lq);
            cp_async16(smem_u32(Bs + row * SSTR + lq),
                       B + (size_t)(n0 + row) * K + k0 + lq);
        }
    };

    issue_load(0, 0);
    asm volatile("cp.async.commit_group;");

    for (int cch = 0; cch < nch; cch++) {
        asm volatile("cp.async.wait_group 0;");
        __syncthreads();   // stage (cch&1) ready; prior compute reads done CTA-wide
        if (cch + 1 < nch) {
            issue_load((cch + 1) & 1, (cch + 1) * BKF);
            asm volatile("cp.async.commit_group;");
        }

        const float* As = smf + (cch & 1) * 2 * STG;
        const float* Bs = As + STG;

#pragma unroll
        for (int kk = 0; kk < 4; kk++) {
            const int kb = kk * 8;
            uint32_t a[2][4];
#pragma unroll
            for (int mi = 0; mi < 2; mi++) {
                const float* ar0 = &As[(wm + mi * 16 + g) * SSTR + kb + t];
                const float* ar1 = &As[(wm + mi * 16 + g + 8) * SSTR + kb + t];
                a[mi][0] = f2tf32(ar0[0]);
                a[mi][1] = f2tf32(ar1[0]);
                a[mi][2] = f2tf32(ar0[4]);
                a[mi][3] = f2tf32(ar1[4]);
            }
            uint32_t b[8][2];
#pragma unroll
            for (int ni = 0; ni < 8; ni++) {
                const float* br = &Bs[(wn + ni * 8 + g) * SSTR + kb + t];
                b[ni][0] = f2tf32(br[0]);
                b[ni][1] = f2tf32(br[4]);
            }
#pragma unroll
            for (int mi = 0; mi < 2; mi++)
#pragma unroll
                for (int ni = 0; ni < 8; ni++)
                    mma_tf32(c[mi][ni][0], c[mi][ni][1], c[mi][ni][2], c[mi][ni][3],
                             a[mi][0], a[mi][1], a[mi][2], a[mi][3],
                             b[ni][0], b[ni][1]);
        }
    }

#pragma unroll
    for (int mi = 0; mi < 2; mi++) {
        const int row = m0 + wm + mi * 16 + g;
#pragma unroll
        for (int ni = 0; ni < 8; ni++) {
            const int col = n0 + wn + ni * 8 + 2 * t;
            *(float2*)(C + (size_t)row * N + col) =
                make_float2(c[mi][ni][0], c[mi][ni][1]);
            *(float2*)(C + (size_t)(row + 8) * N + col) =
                make_float2(c[mi][ni][2], c[mi][ni][3]);
        }
    }
}

// ---------------------------------------------------------------------------
// RoPE in-place on q and k thirds of g_qkv.
// ---------------------------------------------------------------------------
__global__ __launch_bounds__(256) void rope_kernel(
    float* __restrict__ qkv, const float* __restrict__ cs,
    const float* __restrict__ sn)
{
    const int total = BT * HEADS * (HD / 2);
    for (int idx = blockIdx.x * blockDim.x + threadIdx.x; idx < total;
         idx += gridDim.x * blockDim.x) {
        int i   = idx & 31;
        int h   = (idx >> 5) & 15;
        int row = idx >> 9;
        int t   = row & (TSEQ - 1);
        float c = cs[t * 32 + i];
        float s = sn[t * 32 + i];
        float* q = qkv + (size_t)row * QKVDIM + h * HD + 2 * i;
        float2 qv = *(float2*)q;
        *(float2*)q = make_float2(qv.x * c - qv.y * s, qv.x * s + qv.y * c);
        float* k = q + CDIM;
        float2 kv = *(float2*)k;
        *(float2*)k = make_float2(kv.x * c - kv.y * s, kv.x * s + kv.y * c);
    }
}

// ---------------------------------------------------------------------------
// Flash attention, tf32 mma.sync, double-buffered cp.async K/V staging.
// CTA: 128 Q rows x one (b,h); 8 warps x 16 rows. K/V tiles 64 rows.
// K/V stored raw fp32 with XOR-swizzled 64-float rows; cvt at fragment read.
// Pb (Q then P staging) keeps padded stride 68, warp-private P regions.
// ---------------------------------------------------------------------------
#define AM 128
#define AN 64
#define ASTR 68
#define KVSTG (AN * 64)              // floats per K or V stage (4096)
// smem: 2 stages x (K+V) + Pb  = 2*2*4096 + 128*68 floats = 100,352 bytes
#define ATTN_SMEM ((4 * KVSTG + AM * ASTR) * 4)

__global__ __launch_bounds__(256, 2) void attn_mma(
    const float* __restrict__ qkv, float* __restrict__ ao)
{
    extern __shared__ __align__(16) float sm[];
    float* Pb = sm + 4 * KVSTG;         // [128][68]

    // Long-first: block 0 takes the LAST (longest-KV) tile.
    const int m0 = (gridDim.x - 1 - blockIdx.x) * AM;
    const int h  = blockIdx.y;
    const int b  = blockIdx.z;
    const int tid = threadIdx.x;
    const int wid = tid >> 5, lane = tid & 31;
    const int g = lane >> 2, t = lane & 3;
    const int wrow = wid * 16;

    const float* kvb = qkv + (size_t)b * TSEQ * QKVDIM + CDIM + h * HD;

    // Issue K/V tile loads for stage s, key offset n0. 8 cp.async per thread.
    auto issue_kv = [&](int s, int n0) {
        float* Ks = sm + s * 2 * KVSTG;
        float* Vs = Ks + KVSTG;
        const float* kb = kvb + (size_t)n0 * QKVDIM;
        const float* vb = kb + CDIM;
#pragma unroll
        for (int i = 0; i < 4; i++) {
            int e   = tid + i * 256;        // 0..1023
            int row = e >> 4;
            int u   = e & 15;               // 16B unit within row
            int u2  = u ^ (row & 7);        // XOR swizzle
            cp_async16(smem_u32(Ks + row * 64 + u2 * 4),
                       kb + (size_t)row * QKVDIM + u * 4);
            cp_async16(smem_u32(Vs + row * 64 + u2 * 4),
                       vb + (size_t)row * QKVDIM + u * 4);
        }
    };

    const int ntiles = (m0 + AM) / AN;
    issue_kv(0, 0);
    asm volatile("cp.async.commit_group;");

    // ---- Stage Q (scaled, tf32) into Pb, read register fragments ----
    const float* qbase = qkv + ((size_t)(b * TSEQ + m0)) * QKVDIM + h * HD;
    for (int e = tid; e < AM * 16; e += 256) {
        int r = e >> 4, c4 = (e & 15) * 4;
        float4 v = *(const float4*)(qbase + (size_t)r * QKVDIM + c4);
        *(uint4*)(Pb + r * ASTR + c4) = make_uint4(
            f2tf32(v.x * 0.125f), f2tf32(v.y * 0.125f),
            f2tf32(v.z * 0.125f), f2tf32(v.w * 0.125f));
    }
    __syncthreads();
    uint32_t qa[8][4];
#pragma unroll
    for (int kd = 0; kd < 8; kd++) {
        qa[kd][0] = __float_as_uint(Pb[(wrow + g) * ASTR + kd * 8 + t]);
        qa[kd][1] = __float_as_uint(Pb[(wrow + g + 8) * ASTR + kd * 8 + t]);
        qa[kd][2] = __float_as_uint(Pb[(wrow + g) * ASTR + kd * 8 + t + 4]);
        qa[kd][3] = __float_as_uint(Pb[(wrow + g + 8) * ASTR + kd * 8 + t + 4]);
    }

    float o[8][4];
#pragma unroll
    for (int nj = 0; nj < 8; nj++)
#pragma unroll
        for (int r = 0; r < 4; r++) o[nj][r] = 0.0f;
    float mx0 = -1e30f, mx1 = -1e30f, l0 = 0.0f, l1 = 0.0f;

    for (int kt = 0; kt < ntiles; kt++) {
        const int n0 = kt * AN;
        asm volatile("cp.async.wait_group 0;");
        __syncthreads();   // stage (kt&1) ready; prior compute + Q-frag reads done
        if (kt + 1 < ntiles) {
            issue_kv((kt + 1) & 1, n0 + AN);
            asm volatile("cp.async.commit_group;");
        }
        const float* Ks = sm + (kt & 1) * 2 * KVSTG;
        const float* Vs = Ks + KVSTG;

        // ---- S = Q K^T ----
        float s[8][4];
#pragma unroll
        for (int nj = 0; nj < 8; nj++)
#pragma unroll
            for (int r = 0; r < 4; r++) s[nj][r] = 0.0f;
#pragma unroll
        for (int kd = 0; kd < 8; kd++) {
#pragma unroll
            for (int nj = 0; nj < 8; nj++) {
                const float* kr = Ks + (nj * 8 + g) * 64;
                uint32_t b0 = f2tf32(kr[((2 * kd) ^ g) * 4 + t]);
                uint32_t b1 = f2tf32(kr[((2 * kd + 1) ^ g) * 4 + t]);
                mma_tf32(s[nj][0], s[nj][1], s[nj][2], s[nj][3],
                         qa[kd][0], qa[kd][1], qa[kd][2], qa[kd][3], b0, b1);
            }
        }

        // ---- causal mask ----
        const int row0 = m0 + wrow + g;
        const int row1 = row0 + 8;
        if (n0 + AN - 1 > m0 + wrow) {
#pragma unroll
            for (int nj = 0; nj < 8; nj++) {
                int col = n0 + nj * 8 + 2 * t;
                if (col     > row0) s[nj][0] = -1e30f;
                if (col + 1 > row0) s[nj][1] = -1e30f;
                if (col     > row1) s[nj][2] = -1e30f;
                if (col + 1 > row1) s[nj][3] = -1e30f;
            }
        }

        // ---- online softmax (2 rows per thread) ----
        float rm0 = -1e30f, rm1 = -1e30f;
#pragma unroll
        for (int nj = 0; nj < 8; nj++) {
            rm0 = fmaxf(rm0, fmaxf(s[nj][0], s[nj][1]));
            rm1 = fmaxf(rm1, fmaxf(s[nj][2], s[nj][3]));
        }
        rm0 = fmaxf(rm0, __shfl_xor_sync(0xffffffffu, rm0, 1));
        rm0 = fmaxf(rm0, __shfl_xor_sync(0xffffffffu, rm0, 2));
        rm1 = fmaxf(rm1, __shfl_xor_sync(0xffffffffu, rm1, 1));
        rm1 = fmaxf(rm1, __shfl_xor_sync(0xffffffffu, rm1, 2));
        float nm0 = fmaxf(mx0, rm0), nm1 = fmaxf(mx1, rm1);
        float al0 = __expf(mx0 - nm0), al1 = __expf(mx1 - nm1);
        mx0 = nm0; mx1 = nm1;

        float rs0 = 0.0f, rs1 = 0.0f;
#pragma unroll
        for (int nj = 0; nj < 8; nj++) {
            float p0 = __expf(s[nj][0] - nm0);
            float p1 = __expf(s[nj][1] - nm0);
            float p2 = __expf(s[nj][2] - nm1);
            float p3 = __expf(s[nj][3] - nm1);
            rs0 += p0 + p1; rs1 += p2 + p3;
            *(uint2*)(Pb + (wrow + g) * ASTR + nj * 8 + 2 * t) =
                make_uint2(f2tf32(p0), f2tf32(p1));
            *(uint2*)(Pb + (wrow + g + 8) * ASTR + nj * 8 + 2 * t) =
                make_uint2(f2tf32(p2), f2tf32(p3));
        }
        rs0 += __shfl_xor_sync(0xffffffffu, rs0, 1);
        rs0 += __shfl_xor_sync(0xffffffffu, rs0, 2);
        rs1 += __shfl_xor_sync(0xffffffffu, rs1, 1);
        rs1 += __shfl_xor_sync(0xffffffffu, rs1, 2);
        l0 = l0 * al0 + rs0;
        l1 = l1 * al1 + rs1;
#pragma unroll
        for (int nj = 0; nj < 8; nj++) {
            o[nj][0] *= al0; o[nj][1] *= al0;
            o[nj][2] *= al1; o[nj][3] *= al1;
        }
        __syncwarp();   // P visible warp-wide (warp-private region)

        // ---- O += P V ----
#pragma unroll
        for (int kp = 0; kp < 8; kp++) {
            uint32_t pa0 = __float_as_uint(Pb[(wrow + g) * ASTR + kp * 8 + t]);
            uint32_t pa1 = __float_as_uint(Pb[(wrow + g + 8) * ASTR + kp * 8 + t]);
            uint32_t pa2 = __float_as_uint(Pb[(wrow + g) * ASTR + kp * 8 + t + 4]);
            uint32_t pa3 = __float_as_uint(Pb[(wrow + g + 8) * ASTR + kp * 8 + t + 4]);
#pragma unroll
            for (int nj = 0; nj < 8; nj++) {
                const float* vr0 = Vs + (kp * 8 + t) * 64;
                const float* vr1 = Vs + (kp * 8 + t + 4) * 64;
                int c4 = 2 * nj + (g >> 2);
                uint32_t b0 = f2tf32(vr0[(c4 ^ t) * 4 + (g & 3)]);
                uint32_t b1 = f2tf32(vr1[(c4 ^ (t + 4)) * 4 + (g & 3)]);
                mma_tf32(o[nj][0], o[nj][1], o[nj][2], o[nj][3],
                         pa0, pa1, pa2, pa3, b0, b1);
            }
        }
        __syncwarp();   // P loads done before next iteration's P stores
    }

    // ---- normalize + write ----
    const float i0 = 1.0f / l0, i1 = 1.0f / l1;
    const int row0 = m0 + wrow + g;
    float* ob0 = ao + ((size_t)(b * TSEQ + row0)) * CDIM + h * HD;
    float* ob1 = ob0 + 8 * CDIM;
#pragma unroll
    for (int nj = 0; nj < 8; nj++) {
        *(float2*)(ob0 + nj * 8 + 2 * t) = make_float2(o[nj][0] * i0, o[nj][1] * i0);
        *(float2*)(ob1 + nj * 8 + 2 * t) = make_float2(o[nj][2] * i1, o[nj][3] * i1);
    }
}

// ---------------------------------------------------------------------------
// Host launcher
// ---------------------------------------------------------------------------
extern "C" void kernel_launch(void* const* d_in, const int* in_sizes, int n_in,
                              void* d_out, int out_size)
{
    const float* x       = (const float*)d_in[0];  // [2,2048,1024]
    const float* f_cos   = (const float*)d_in[1];  // [2048,32]
    const float* f_sin   = (const float*)d_in[2];  // [2048,32]
    const float* qkv_w   = (const float*)d_in[3];  // [3072,1024]
    const float* proj_w  = (const float*)d_in[4];  // [1024,1024]
    float* out = (float*)d_out;

    float *qkv_ptr, *ao_ptr;
    cudaGetSymbolAddress((void**)&qkv_ptr, g_qkv);
    cudaGetSymbolAddress((void**)&ao_ptr, g_ao);

    cudaFuncSetAttribute(gemm_tf32_nt,
                         cudaFuncAttributeMaxDynamicSharedMemorySize, GEMM_SMEM);
    cudaFuncSetAttribute(attn_mma,
                         cudaFuncAttributeMaxDynamicSharedMemorySize, ATTN_SMEM);

    // 1) QKV projection (tf32 mma.sync, cp.async pipelined)
    {
        dim3 grid(QKVDIM / TN, BT / TM);
        gemm_tf32_nt<<<grid, 256, GEMM_SMEM>>>(x, qkv_w, qkv_ptr, BT, QKVDIM, CDIM);
    }

    // 2) RoPE
    rope_kernel<<<2048, 256>>>(qkv_ptr, f_cos, f_sin);

    // 3) Causal flash attention (tf32 mma.sync, cp.async K/V pipeline)
    {
        dim3 grid(TSEQ / AM, HEADS, BATCH);
        attn_mma<<<grid, 256, ATTN_SMEM>>>(qkv_ptr, ao_ptr);
    }

    // 4) Output projection (tf32 mma.sync, cp.async pipelined)
    {
        dim3 grid(CDIM / TN, BT / TM);
        gemm_tf32_nt<<<grid, 256, GEMM_SMEM>>>(ao_ptr, proj_w, out, BT, CDIM, CDIM);
    }
}

// round 11
// speedup vs baseline: 4.1652x; 1.0878x over previous
#include <cuda_runtime.h>
#include <cstdint>
#include <math.h>

// Problem constants
#define BATCH   2
#define TSEQ    2048
#define CDIM    1024
#define HEADS   16
#define HD      64
#define BT      (BATCH * TSEQ)          // 4096 rows
#define QKVDIM  (3 * CDIM)              // 3072

// Scratch (allocation-free rule: __device__ globals)
__device__ float g_qkv[(size_t)BT * QKVDIM];    // [4096, 3072]
__device__ float g_ao [(size_t)BT * CDIM];      // [4096, 1024] (tf32-rounded)
__device__ float g_xr [(size_t)BT * CDIM];      // x, tf32-rounded
__device__ float g_wq [(size_t)QKVDIM * CDIM];  // qkv_w, tf32-rounded
__device__ float g_wp [(size_t)CDIM * CDIM];    // proj_w, tf32-rounded

__device__ __forceinline__ uint32_t f2tf32(float v) {
    uint32_t u;
    asm("cvt.rna.tf32.f32 %0, %1;" : "=r"(u) : "f"(v));
    return u;
}
__device__ __forceinline__ float rtf(float v) {     // tf32-round, as float
    return __uint_as_float(f2tf32(v));
}
__device__ __forceinline__ uint32_t smem_u32(const void* p) {
    uint32_t a;
    asm("{ .reg .u64 t; cvta.to.shared.u64 t, %1; cvt.u32.u64 %0, t; }"
        : "=r"(a) : "l"(p));
    return a;
}
__device__ __forceinline__ void cp_async16(uint32_t dst, const void* src) {
    asm volatile("cp.async.cg.shared.global [%0], [%1], 16;"
                 :: "r"(dst), "l"(src));
}

__device__ __forceinline__ void mma_tf32(
    float& c0, float& c1, float& c2, float& c3,
    uint32_t a0, uint32_t a1, uint32_t a2, uint32_t a3,
    uint32_t b0, uint32_t b1)
{
    asm volatile(
        "mma.sync.aligned.m16n8k8.row.col.f32.tf32.tf32.f32 "
        "{%0,%1,%2,%3}, {%4,%5,%6,%7}, {%8,%9}, {%0,%1,%2,%3};"
        : "+f"(c0), "+f"(c1), "+f"(c2), "+f"(c3)
        : "r"(a0), "r"(a1), "r"(a2), "r"(a3), "r"(b0), "r"(b1));
}

// ---------------------------------------------------------------------------
// Pre-round pass: dst[i] = tf32_rna(src[i]) (vectorized)
// ---------------------------------------------------------------------------
__global__ __launch_bounds__(256) void round_tf32_kernel(
    const float4* __restrict__ src, float4* __restrict__ dst, int n4)
{
    for (int i = blockIdx.x * blockDim.x + threadIdx.x; i < n4;
         i += gridDim.x * blockDim.x) {
        float4 v = src[i];
        dst[i] = make_float4(rtf(v.x), rtf(v.y), rtf(v.z), rtf(v.w));
    }
}

// ---------------------------------------------------------------------------
// TF32 mma.sync GEMM, 2-stage cp.async pipeline, one barrier/chunk.
// Inputs MUST be pre-rounded to tf32 (raw bits fed to mma).
// C[M,N] = A[M,K] @ B[N,K]^T. 128x128 CTA tile, BK=32, 8 warps (4Mx2N).
// ---------------------------------------------------------------------------
#define TM  128
#define TN  128
#define BKF 32
#define SSTR 36
#define STG (TM * SSTR)              // floats per matrix per stage (4608)
#define GEMM_SMEM (2 * 2 * STG * 4)  // 73728 bytes

__global__ __launch_bounds__(256, 2) void gemm_tf32_nt(
    const float* __restrict__ A, const float* __restrict__ B,
    float* __restrict__ C, int M, int N, int K)
{
    extern __shared__ __align__(16) float smf[];

    const int tid  = threadIdx.x;
    const int wid  = tid >> 5;
    const int lane = tid & 31;
    const int g = lane >> 2;
    const int t = lane & 3;
    const int wm = (wid & 3) * 32;
    const int wn = (wid >> 2) * 64;
    const int m0 = blockIdx.y * TM;
    const int n0 = blockIdx.x * TN;

    const int lrow = tid >> 3;
    const int lq   = (tid & 7) * 4;

    float c[2][8][4];
#pragma unroll
    for (int mi = 0; mi < 2; mi++)
#pragma unroll
        for (int ni = 0; ni < 8; ni++)
#pragma unroll
            for (int r = 0; r < 4; r++) c[mi][ni][r] = 0.0f;

    const int nch = K / BKF;

    auto issue_load = [&](int s, int k0) {
        float* As = smf + s * 2 * STG;
        float* Bs = As + STG;
#pragma unroll
        for (int i = 0; i < 4; i++) {
            int row = lrow + i * 32;
            cp_async16(smem_u32(As + row * SSTR + lq),
                       A + (size_t)(m0 + row) * K + k0 + lq);
            cp_async16(smem_u32(Bs + row * SSTR + lq),
                       B + (size_t)(n0 + row) * K + k0 + lq);
        }
    };

    issue_load(0, 0);
    asm volatile("cp.async.commit_group;");

    for (int cch = 0; cch < nch; cch++) {
        asm volatile("cp.async.wait_group 0;");
        __syncthreads();
        if (cch + 1 < nch) {
            issue_load((cch + 1) & 1, (cch + 1) * BKF);
            asm volatile("cp.async.commit_group;");
        }

        const float* As = smf + (cch & 1) * 2 * STG;
        const float* Bs = As + STG;

#pragma unroll
        for (int kk = 0; kk < 4; kk++) {
            const int kb = kk * 8;
            uint32_t a[2][4];
#pragma unroll
            for (int mi = 0; mi < 2; mi++) {
                const float* ar0 = &As[(wm + mi * 16 + g) * SSTR + kb + t];
                const float* ar1 = &As[(wm + mi * 16 + g + 8) * SSTR + kb + t];
                a[mi][0] = __float_as_uint(ar0[0]);
                a[mi][1] = __float_as_uint(ar1[0]);
                a[mi][2] = __float_as_uint(ar0[4]);
                a[mi][3] = __float_as_uint(ar1[4]);
            }
            uint32_t b[8][2];
#pragma unroll
            for (int ni = 0; ni < 8; ni++) {
                const float* br = &Bs[(wn + ni * 8 + g) * SSTR + kb + t];
                b[ni][0] = __float_as_uint(br[0]);
                b[ni][1] = __float_as_uint(br[4]);
            }
#pragma unroll
            for (int mi = 0; mi < 2; mi++)
#pragma unroll
                for (int ni = 0; ni < 8; ni++)
                    mma_tf32(c[mi][ni][0], c[mi][ni][1], c[mi][ni][2], c[mi][ni][3],
                             a[mi][0], a[mi][1], a[mi][2], a[mi][3],
                             b[ni][0], b[ni][1]);
        }
    }

#pragma unroll
    for (int mi = 0; mi < 2; mi++) {
        const int row = m0 + wm + mi * 16 + g;
#pragma unroll
        for (int ni = 0; ni < 8; ni++) {
            const int col = n0 + wn + ni * 8 + 2 * t;
            *(float2*)(C + (size_t)row * N + col) =
                make_float2(c[mi][ni][0], c[mi][ni][1]);
            *(float2*)(C + (size_t)(row + 8) * N + col) =
                make_float2(c[mi][ni][2], c[mi][ni][3]);
        }
    }
}

// ---------------------------------------------------------------------------
// RoPE in-place on q,k thirds; q/k outputs AND the v third are tf32-rounded
// so the attention kernel can feed raw bits to mma.
// ---------------------------------------------------------------------------
__global__ __launch_bounds__(256) void rope_kernel(
    float* __restrict__ qkv, const float* __restrict__ cs,
    const float* __restrict__ sn)
{
    const int total = BT * HEADS * (HD / 2);
    for (int idx = blockIdx.x * blockDim.x + threadIdx.x; idx < total;
         idx += gridDim.x * blockDim.x) {
        int i   = idx & 31;
        int h   = (idx >> 5) & 15;
        int row = idx >> 9;
        int t   = row & (TSEQ - 1);
        float c = cs[t * 32 + i];
        float s = sn[t * 32 + i];
        float* q = qkv + (size_t)row * QKVDIM + h * HD + 2 * i;
        float2 qv = *(float2*)q;
        *(float2*)q = make_float2(rtf(qv.x * c - qv.y * s),
                                  rtf(qv.x * s + qv.y * c));
        float* k = q + CDIM;
        float2 kv = *(float2*)k;
        *(float2*)k = make_float2(rtf(kv.x * c - kv.y * s),
                                  rtf(kv.x * s + kv.y * c));
        float* v = q + 2 * CDIM;
        float2 vv = *(float2*)v;
        *(float2*)v = make_float2(rtf(vv.x), rtf(vv.y));
    }
}

// ---------------------------------------------------------------------------
// Flash attention, tf32 mma.sync, double-buffered cp.async K/V staging.
// qkv q/k/v thirds are pre-rounded tf32 -> raw bits to mma (no cvt in loop).
// Output written tf32-rounded for the proj GEMM.
// ---------------------------------------------------------------------------
#define AM 128
#define AN 64
#define ASTR 68
#define KVSTG (AN * 64)              // floats per K or V stage (4096)
#define ATTN_SMEM ((4 * KVSTG + AM * ASTR) * 4)   // 100,352 bytes

__global__ __launch_bounds__(256, 2) void attn_mma(
    const float* __restrict__ qkv, float* __restrict__ ao)
{
    extern __shared__ __align__(16) float sm[];
    float* Pb = sm + 4 * KVSTG;         // [128][68]

    // Long-first: block 0 takes the LAST (longest-KV) tile.
    const int m0 = (gridDim.x - 1 - blockIdx.x) * AM;
    const int h  = blockIdx.y;
    const int b  = blockIdx.z;
    const int tid = threadIdx.x;
    const int wid = tid >> 5, lane = tid & 31;
    const int g = lane >> 2, t = lane & 3;
    const int wrow = wid * 16;

    const float* kvb = qkv + (size_t)b * TSEQ * QKVDIM + CDIM + h * HD;

    auto issue_kv = [&](int s, int n0) {
        float* Ks = sm + s * 2 * KVSTG;
        float* Vs = Ks + KVSTG;
        const float* kb = kvb + (size_t)n0 * QKVDIM;
        const float* vb = kb + CDIM;
#pragma unroll
        for (int i = 0; i < 4; i++) {
            int e   = tid + i * 256;
            int row = e >> 4;
            int u   = e & 15;
            int u2  = u ^ (row & 7);
            cp_async16(smem_u32(Ks + row * 64 + u2 * 4),
                       kb + (size_t)row * QKVDIM + u * 4);
            cp_async16(smem_u32(Vs + row * 64 + u2 * 4),
                       vb + (size_t)row * QKVDIM + u * 4);
        }
    };

    const int ntiles = (m0 + AM) / AN;
    issue_kv(0, 0);
    asm volatile("cp.async.commit_group;");

    // ---- Stage Q (x0.125, exact on tf32 values) into Pb ----
    const float* qbase = qkv + ((size_t)(b * TSEQ + m0)) * QKVDIM + h * HD;
    for (int e = tid; e < AM * 16; e += 256) {
        int r = e >> 4, c4 = (e & 15) * 4;
        float4 v = *(const float4*)(qbase + (size_t)r * QKVDIM + c4);
        *(float4*)(Pb + r * ASTR + c4) = make_float4(
            v.x * 0.125f, v.y * 0.125f, v.z * 0.125f, v.w * 0.125f);
    }
    __syncthreads();
    uint32_t qa[8][4];
#pragma unroll
    for (int kd = 0; kd < 8; kd++) {
        qa[kd][0] = __float_as_uint(Pb[(wrow + g) * ASTR + kd * 8 + t]);
        qa[kd][1] = __float_as_uint(Pb[(wrow + g + 8) * ASTR + kd * 8 + t]);
        qa[kd][2] = __float_as_uint(Pb[(wrow + g) * ASTR + kd * 8 + t + 4]);
        qa[kd][3] = __float_as_uint(Pb[(wrow + g + 8) * ASTR + kd * 8 + t + 4]);
    }

    float o[8][4];
#pragma unroll
    for (int nj = 0; nj < 8; nj++)
#pragma unroll
        for (int r = 0; r < 4; r++) o[nj][r] = 0.0f;
    float mx0 = -1e30f, mx1 = -1e30f, l0 = 0.0f, l1 = 0.0f;

    for (int kt = 0; kt < ntiles; kt++) {
        const int n0 = kt * AN;
        asm volatile("cp.async.wait_group 0;");
        __syncthreads();
        if (kt + 1 < ntiles) {
            issue_kv((kt + 1) & 1, n0 + AN);
            asm volatile("cp.async.commit_group;");
        }
        const float* Ks = sm + (kt & 1) * 2 * KVSTG;
        const float* Vs = Ks + KVSTG;

        // ---- S = Q K^T (raw tf32 bits) ----
        float s[8][4];
#pragma unroll
        for (int nj = 0; nj < 8; nj++)
#pragma unroll
            for (int r = 0; r < 4; r++) s[nj][r] = 0.0f;
#pragma unroll
        for (int kd = 0; kd < 8; kd++) {
#pragma unroll
            for (int nj = 0; nj < 8; nj++) {
                const float* kr = Ks + (nj * 8 + g) * 64;
                uint32_t b0 = __float_as_uint(kr[((2 * kd) ^ g) * 4 + t]);
                uint32_t b1 = __float_as_uint(kr[((2 * kd + 1) ^ g) * 4 + t]);
                mma_tf32(s[nj][0], s[nj][1], s[nj][2], s[nj][3],
                         qa[kd][0], qa[kd][1], qa[kd][2], qa[kd][3], b0, b1);
            }
        }

        // ---- causal mask ----
        const int row0 = m0 + wrow + g;
        const int row1 = row0 + 8;
        if (n0 + AN - 1 > m0 + wrow) {
#pragma unroll
            for (int nj = 0; nj < 8; nj++) {
                int col = n0 + nj * 8 + 2 * t;
                if (col     > row0) s[nj][0] = -1e30f;
                if (col + 1 > row0) s[nj][1] = -1e30f;
                if (col     > row1) s[nj][2] = -1e30f;
                if (col + 1 > row1) s[nj][3] = -1e30f;
            }
        }

        // ---- online softmax (2 rows per thread) ----
        float rm0 = -1e30f, rm1 = -1e30f;
#pragma unroll
        for (int nj = 0; nj < 8; nj++) {
            rm0 = fmaxf(rm0, fmaxf(s[nj][0], s[nj][1]));
            rm1 = fmaxf(rm1, fmaxf(s[nj][2], s[nj][3]));
        }
        rm0 = fmaxf(rm0, __shfl_xor_sync(0xffffffffu, rm0, 1));
        rm0 = fmaxf(rm0, __shfl_xor_sync(0xffffffffu, rm0, 2));
        rm1 = fmaxf(rm1, __shfl_xor_sync(0xffffffffu, rm1, 1));
        rm1 = fmaxf(rm1, __shfl_xor_sync(0xffffffffu, rm1, 2));
        float nm0 = fmaxf(mx0, rm0), nm1 = fmaxf(mx1, rm1);
        float al0 = __expf(mx0 - nm0), al1 = __expf(mx1 - nm1);
        mx0 = nm0; mx1 = nm1;

        float rs0 = 0.0f, rs1 = 0.0f;
#pragma unroll
        for (int nj = 0; nj < 8; nj++) {
            float p0 = __expf(s[nj][0] - nm0);
            float p1 = __expf(s[nj][1] - nm0);
            float p2 = __expf(s[nj][2] - nm1);
            float p3 = __expf(s[nj][3] - nm1);
            rs0 += p0 + p1; rs1 += p2 + p3;
            *(uint2*)(Pb + (wrow + g) * ASTR + nj * 8 + 2 * t) =
                make_uint2(f2tf32(p0), f2tf32(p1));
            *(uint2*)(Pb + (wrow + g + 8) * ASTR + nj * 8 + 2 * t) =
                make_uint2(f2tf32(p2), f2tf32(p3));
        }
        rs0 += __shfl_xor_sync(0xffffffffu, rs0, 1);
        rs0 += __shfl_xor_sync(0xffffffffu, rs0, 2);
        rs1 += __shfl_xor_sync(0xffffffffu, rs1, 1);
        rs1 += __shfl_xor_sync(0xffffffffu, rs1, 2);
        l0 = l0 * al0 + rs0;
        l1 = l1 * al1 + rs1;
#pragma unroll
        for (int nj = 0; nj < 8; nj++) {
            o[nj][0] *= al0; o[nj][1] *= al0;
            o[nj][2] *= al1; o[nj][3] *= al1;
        }
        __syncwarp();

        // ---- O += P V (raw tf32 bits) ----
#pragma unroll
        for (int kp = 0; kp < 8; kp++) {
            uint32_t pa0 = __float_as_uint(Pb[(wrow + g) * ASTR + kp * 8 + t]);
            uint32_t pa1 = __float_as_uint(Pb[(wrow + g + 8) * ASTR + kp * 8 + t]);
            uint32_t pa2 = __float_as_uint(Pb[(wrow + g) * ASTR + kp * 8 + t + 4]);
            uint32_t pa3 = __float_as_uint(Pb[(wrow + g + 8) * ASTR + kp * 8 + t + 4]);
#pragma unroll
            for (int nj = 0; nj < 8; nj++) {
                const float* vr0 = Vs + (kp * 8 + t) * 64;
                const float* vr1 = Vs + (kp * 8 + t + 4) * 64;
                int c4 = 2 * nj + (g >> 2);
                uint32_t b0 = __float_as_uint(vr0[(c4 ^ t) * 4 + (g & 3)]);
                uint32_t b1 = __float_as_uint(vr1[(c4 ^ (t + 4)) * 4 + (g & 3)]);
                mma_tf32(o[nj][0], o[nj][1], o[nj][2], o[nj][3],
                         pa0, pa1, pa2, pa3, b0, b1);
            }
        }
        __syncwarp();
    }

    // ---- normalize + write (tf32-rounded for the proj GEMM) ----
    const float i0 = 1.0f / l0, i1 = 1.0f / l1;
    const int row0 = m0 + wrow + g;
    float* ob0 = ao + ((size_t)(b * TSEQ + row0)) * CDIM + h * HD;
    float* ob1 = ob0 + 8 * CDIM;
#pragma unroll
    for (int nj = 0; nj < 8; nj++) {
        *(float2*)(ob0 + nj * 8 + 2 * t) =
            make_float2(rtf(o[nj][0] * i0), rtf(o[nj][1] * i0));
        *(float2*)(ob1 + nj * 8 + 2 * t) =
            make_float2(rtf(o[nj][2] * i1), rtf(o[nj][3] * i1));
    }
}

// ---------------------------------------------------------------------------
// Host launcher
// ---------------------------------------------------------------------------
extern "C" void kernel_launch(void* const* d_in, const int* in_sizes, int n_in,
                              void* d_out, int out_size)
{
    const float* x       = (const float*)d_in[0];  // [2,2048,1024]
    const float* f_cos   = (const float*)d_in[1];  // [2048,32]
    const float* f_sin   = (const float*)d_in[2];  // [2048,32]
    const float* qkv_w   = (const float*)d_in[3];  // [3072,1024]
    const float* proj_w  = (const float*)d_in[4];  // [1024,1024]
    float* out = (float*)d_out;

    float *qkv_ptr, *ao_ptr, *xr_ptr, *wq_ptr, *wp_ptr;
    cudaGetSymbolAddress((void**)&qkv_ptr, g_qkv);
    cudaGetSymbolAddress((void**)&ao_ptr,  g_ao);
    cudaGetSymbolAddress((void**)&xr_ptr,  g_xr);
    cudaGetSymbolAddress((void**)&wq_ptr,  g_wq);
    cudaGetSymbolAddress((void**)&wp_ptr,  g_wp);

    cudaFuncSetAttribute(gemm_tf32_nt,
                         cudaFuncAttributeMaxDynamicSharedMemorySize, GEMM_SMEM);
    cudaFuncSetAttribute(attn_mma,
                         cudaFuncAttributeMaxDynamicSharedMemorySize, ATTN_SMEM);

    // 0) Pre-round x and weights to tf32
    round_tf32_kernel<<<1024, 256>>>((const float4*)x, (float4*)xr_ptr,
                                     BT * CDIM / 4);
    round_tf32_kernel<<<1024, 256>>>((const float4*)qkv_w, (float4*)wq_ptr,
                                     QKVDIM * CDIM / 4);
    round_tf32_kernel<<<1024, 256>>>((const float4*)proj_w, (float4*)wp_ptr,
                                     CDIM * CDIM / 4);

    // 1) QKV projection (tf32 mma.sync, cp.async pipelined, no in-loop cvt)
    {
        dim3 grid(QKVDIM / TN, BT / TM);
        gemm_tf32_nt<<<grid, 256, GEMM_SMEM>>>(xr_ptr, wq_ptr, qkv_ptr,
                                               BT, QKVDIM, CDIM);
    }

    // 2) RoPE (+ tf32 rounding of q,k,v)
    rope_kernel<<<2048, 256>>>(qkv_ptr, f_cos, f_sin);

    // 3) Causal flash attention (tf32 mma.sync, raw-bit operands)
    {
        dim3 grid(TSEQ / AM, HEADS, BATCH);
        attn_mma<<<grid, 256, ATTN_SMEM>>>(qkv_ptr, ao_ptr);
    }

    // 4) Output projection
    {
        dim3 grid(CDIM / TN, BT / TM);
        gemm_tf32_nt<<<grid, 256, GEMM_SMEM>>>(ao_ptr, wp_ptr, out,
                                               BT, CDIM, CDIM);
    }
}

// round 12
// speedup vs baseline: 4.4489x; 1.0681x over previous
#include <cuda_runtime.h>
#include <cstdint>
#include <math.h>

// Problem constants
#define BATCH   2
#define TSEQ    2048
#define CDIM    1024
#define HEADS   16
#define HD      64
#define BT      (BATCH * TSEQ)          // 4096 rows
#define QKVDIM  (3 * CDIM)              // 3072

// Scratch (allocation-free rule: __device__ globals)
__device__ float g_qkv[(size_t)BT * QKVDIM];    // [4096, 3072]
__device__ float g_ao [(size_t)BT * CDIM];      // [4096, 1024] (tf32-rounded)
__device__ float g_xr [(size_t)BT * CDIM];      // x, tf32-rounded
__device__ float g_wq [(size_t)QKVDIM * CDIM];  // qkv_w, tf32-rounded
__device__ float g_wp [(size_t)CDIM * CDIM];    // proj_w, tf32-rounded

__device__ __forceinline__ uint32_t f2tf32(float v) {
    uint32_t u;
    asm("cvt.rna.tf32.f32 %0, %1;" : "=r"(u) : "f"(v));
    return u;
}
__device__ __forceinline__ float rtf(float v) {
    return __uint_as_float(f2tf32(v));
}
__device__ __forceinline__ uint32_t smem_u32(const void* p) {
    uint32_t a;
    asm("{ .reg .u64 t; cvta.to.shared.u64 t, %1; cvt.u32.u64 %0, t; }"
        : "=r"(a) : "l"(p));
    return a;
}
__device__ __forceinline__ void cp_async16(uint32_t dst, const void* src) {
    asm volatile("cp.async.cg.shared.global [%0], [%1], 16;"
                 :: "r"(dst), "l"(src));
}
__device__ __forceinline__ void ldsm4(uint32_t& r0, uint32_t& r1,
                                      uint32_t& r2, uint32_t& r3, uint32_t addr) {
    asm volatile("ldmatrix.sync.aligned.m8n8.x4.shared.b16 {%0,%1,%2,%3}, [%4];"
                 : "=r"(r0), "=r"(r1), "=r"(r2), "=r"(r3) : "r"(addr));
}

__device__ __forceinline__ void mma_tf32(
    float& c0, float& c1, float& c2, float& c3,
    uint32_t a0, uint32_t a1, uint32_t a2, uint32_t a3,
    uint32_t b0, uint32_t b1)
{
    asm volatile(
        "mma.sync.aligned.m16n8k8.row.col.f32.tf32.tf32.f32 "
        "{%0,%1,%2,%3}, {%4,%5,%6,%7}, {%8,%9}, {%0,%1,%2,%3};"
        : "+f"(c0), "+f"(c1), "+f"(c2), "+f"(c3)
        : "r"(a0), "r"(a1), "r"(a2), "r"(a3), "r"(b0), "r"(b1));
}

// ---------------------------------------------------------------------------
// Pre-round pass: dst[i] = tf32_rna(src[i])
// ---------------------------------------------------------------------------
__global__ __launch_bounds__(256) void round_tf32_kernel(
    const float4* __restrict__ src, float4* __restrict__ dst, int n4)
{
    for (int i = blockIdx.x * blockDim.x + threadIdx.x; i < n4;
         i += gridDim.x * blockDim.x) {
        float4 v = src[i];
        dst[i] = make_float4(rtf(v.x), rtf(v.y), rtf(v.z), rtf(v.w));
    }
}

// ---------------------------------------------------------------------------
// TF32 mma.sync GEMM, 3-stage cp.async pipeline, ldmatrix fragment loads.
// Inputs pre-rounded to tf32 (raw bits to mma).
// C[M,N] = A[M,K] @ B[N,K]^T. 128x128 CTA tile, BK=32, 8 warps (4Mx2N).
// ---------------------------------------------------------------------------
#define TM  128
#define TN  128
#define BKF 32
#define SSTR 36
#define STG (TM * SSTR)                  // floats per matrix per stage (4608)
#define NSTAGE 3
#define GEMM_SMEM (NSTAGE * 2 * STG * 4) // 110592 bytes

__global__ __launch_bounds__(256, 2) void gemm_tf32_nt(
    const float* __restrict__ A, const float* __restrict__ B,
    float* __restrict__ C, int M, int N, int K)
{
    extern __shared__ __align__(16) float smf[];

    const int tid  = threadIdx.x;
    const int wid  = tid >> 5;
    const int lane = tid & 31;
    const int g = lane >> 2;
    const int t = lane & 3;
    const int wm = (wid & 3) * 32;
    const int wn = (wid >> 2) * 64;
    const int m0 = blockIdx.y * TM;
    const int n0 = blockIdx.x * TN;

    const int lrow = tid >> 3;
    const int lq   = (tid & 7) * 4;

    // ldmatrix per-lane base offsets (in floats, relative to stage base)
    // A frag (mi): matrices {a0,a1,a2,a3} = rows (lane&15), col +4*(lane>=16)
    const int aoff0 = (wm + (lane & 15)) * SSTR + ((lane & 16) >> 2);
    // B frag (ni-pair p): m0=b0(2p) m1=b1(2p) m2=b0(2p+1) m3=b1(2p+1)
    const int boff0 = (wn + ((lane & 16) >> 1) + (lane & 7)) * SSTR
                    + ((lane & 8) >> 1);

    float c[2][8][4];
#pragma unroll
    for (int mi = 0; mi < 2; mi++)
#pragma unroll
        for (int ni = 0; ni < 8; ni++)
#pragma unroll
            for (int r = 0; r < 4; r++) c[mi][ni][r] = 0.0f;

    const int nch = K / BKF;

    auto issue_load = [&](int s, int k0) {
        float* As = smf + s * 2 * STG;
        float* Bs = As + STG;
#pragma unroll
        for (int i = 0; i < 4; i++) {
            int row = lrow + i * 32;
            cp_async16(smem_u32(As + row * SSTR + lq),
                       A + (size_t)(m0 + row) * K + k0 + lq);
            cp_async16(smem_u32(Bs + row * SSTR + lq),
                       B + (size_t)(n0 + row) * K + k0 + lq);
        }
    };

    issue_load(0, 0);
    asm volatile("cp.async.commit_group;");
    if (nch > 1) issue_load(1, BKF);
    asm volatile("cp.async.commit_group;");

    for (int cch = 0; cch < nch; cch++) {
        asm volatile("cp.async.wait_group 1;");
        __syncthreads();   // stage (cch%3) ready; reads of stage (cch+2)%3 done
        if (cch + 2 < nch) issue_load((cch + 2) % NSTAGE, (cch + 2) * BKF);
        asm volatile("cp.async.commit_group;");   // may be empty; keeps count

        const float* As = smf + (cch % NSTAGE) * 2 * STG;
        const float* Bs = As + STG;
        const uint32_t a_base = smem_u32(As) + aoff0 * 4;
        const uint32_t b_base = smem_u32(Bs) + boff0 * 4;

#pragma unroll
        for (int kk = 0; kk < 4; kk++) {
            const int kb = kk * 8;
            uint32_t a[2][4];
#pragma unroll
            for (int mi = 0; mi < 2; mi++)
                ldsm4(a[mi][0], a[mi][1], a[mi][2], a[mi][3],
                      a_base + (mi * 16 * SSTR + kb) * 4);
            uint32_t b[8][2];
#pragma unroll
            for (int p = 0; p < 4; p++)
                ldsm4(b[2 * p][0], b[2 * p][1], b[2 * p + 1][0], b[2 * p + 1][1],
                      b_base + (p * 16 * SSTR + kb) * 4);
#pragma unroll
            for (int mi = 0; mi < 2; mi++)
#pragma unroll
                for (int ni = 0; ni < 8; ni++)
                    mma_tf32(c[mi][ni][0], c[mi][ni][1], c[mi][ni][2], c[mi][ni][3],
                             a[mi][0], a[mi][1], a[mi][2], a[mi][3],
                             b[ni][0], b[ni][1]);
        }
    }

#pragma unroll
    for (int mi = 0; mi < 2; mi++) {
        const int row = m0 + wm + mi * 16 + g;
#pragma unroll
        for (int ni = 0; ni < 8; ni++) {
            const int col = n0 + wn + ni * 8 + 2 * t;
            *(float2*)(C + (size_t)row * N + col) =
                make_float2(c[mi][ni][0], c[mi][ni][1]);
            *(float2*)(C + (size_t)(row + 8) * N + col) =
                make_float2(c[mi][ni][2], c[mi][ni][3]);
        }
    }
}

// ---------------------------------------------------------------------------
// RoPE in-place; q/k outputs and v third tf32-rounded.
// ---------------------------------------------------------------------------
__global__ __launch_bounds__(256) void rope_kernel(
    float* __restrict__ qkv, const float* __restrict__ cs,
    const float* __restrict__ sn)
{
    const int total = BT * HEADS * (HD / 2);
    for (int idx = blockIdx.x * blockDim.x + threadIdx.x; idx < total;
         idx += gridDim.x * blockDim.x) {
        int i   = idx & 31;
        int h   = (idx >> 5) & 15;
        int row = idx >> 9;
        int t   = row & (TSEQ - 1);
        float c = cs[t * 32 + i];
        float s = sn[t * 32 + i];
        float* q = qkv + (size_t)row * QKVDIM + h * HD + 2 * i;
        float2 qv = *(float2*)q;
        *(float2*)q = make_float2(rtf(qv.x * c - qv.y * s),
                                  rtf(qv.x * s + qv.y * c));
        float* k = q + CDIM;
        float2 kv = *(float2*)k;
        *(float2*)k = make_float2(rtf(kv.x * c - kv.y * s),
                                  rtf(kv.x * s + kv.y * c));
        float* v = q + 2 * CDIM;
        float2 vv = *(float2*)v;
        *(float2*)v = make_float2(rtf(vv.x), rtf(vv.y));
    }
}

// ---------------------------------------------------------------------------
// Flash attention, tf32 mma.sync, double-buffered cp.async K/V staging,
// ldmatrix K-fragment loads. Pre-rounded operands -> raw bits to mma.
// ---------------------------------------------------------------------------
#define AM 128
#define AN 64
#define ASTR 68
#define KVSTG (AN * 64)              // floats per K or V stage (4096)
#define ATTN_SMEM ((4 * KVSTG + AM * ASTR) * 4)   // 100,352 bytes

__global__ __launch_bounds__(256, 2) void attn_mma(
    const float* __restrict__ qkv, float* __restrict__ ao)
{
    extern __shared__ __align__(16) float sm[];
    float* Pb = sm + 4 * KVSTG;         // [128][68]

    // Long-first: block 0 takes the LAST (longest-KV) tile.
    const int m0 = (gridDim.x - 1 - blockIdx.x) * AM;
    const int h  = blockIdx.y;
    const int b  = blockIdx.z;
    const int tid = threadIdx.x;
    const int wid = tid >> 5, lane = tid & 31;
    const int g = lane >> 2, t = lane & 3;
    const int wrow = wid * 16;
    const int rl = lane & 7, midx = lane >> 3;   // ldmatrix lane decomposition

    const float* kvb = qkv + (size_t)b * TSEQ * QKVDIM + CDIM + h * HD;

    auto issue_kv = [&](int s, int n0) {
        float* Ks = sm + s * 2 * KVSTG;
        float* Vs = Ks + KVSTG;
        const float* kb = kvb + (size_t)n0 * QKVDIM;
        const float* vb = kb + CDIM;
#pragma unroll
        for (int i = 0; i < 4; i++) {
            int e   = tid + i * 256;
            int row = e >> 4;
            int u   = e & 15;
            int u2  = u ^ (row & 7);
            cp_async16(smem_u32(Ks + row * 64 + u2 * 4),
                       kb + (size_t)row * QKVDIM + u * 4);
            cp_async16(smem_u32(Vs + row * 64 + u2 * 4),
                       vb + (size_t)row * QKVDIM + u * 4);
        }
    };

    const int ntiles = (m0 + AM) / AN;
    issue_kv(0, 0);
    asm volatile("cp.async.commit_group;");

    // ---- Stage Q (x0.125, exact on tf32 values) into Pb ----
    const float* qbase = qkv + ((size_t)(b * TSEQ + m0)) * QKVDIM + h * HD;
    for (int e = tid; e < AM * 16; e += 256) {
        int r = e >> 4, c4 = (e & 15) * 4;
        float4 v = *(const float4*)(qbase + (size_t)r * QKVDIM + c4);
        *(float4*)(Pb + r * ASTR + c4) = make_float4(
            v.x * 0.125f, v.y * 0.125f, v.z * 0.125f, v.w * 0.125f);
    }
    __syncthreads();
    uint32_t qa[8][4];
#pragma unroll
    for (int kd = 0; kd < 8; kd++) {
        qa[kd][0] = __float_as_uint(Pb[(wrow + g) * ASTR + kd * 8 + t]);
        qa[kd][1] = __float_as_uint(Pb[(wrow + g + 8) * ASTR + kd * 8 + t]);
        qa[kd][2] = __float_as_uint(Pb[(wrow + g) * ASTR + kd * 8 + t + 4]);
        qa[kd][3] = __float_as_uint(Pb[(wrow + g + 8) * ASTR + kd * 8 + t + 4]);
    }

    float o[8][4];
#pragma unroll
    for (int nj = 0; nj < 8; nj++)
#pragma unroll
        for (int r = 0; r < 4; r++) o[nj][r] = 0.0f;
    float mx0 = -1e30f, mx1 = -1e30f, l0 = 0.0f, l1 = 0.0f;

    for (int kt = 0; kt < ntiles; kt++) {
        const int n0 = kt * AN;
        asm volatile("cp.async.wait_group 0;");
        __syncthreads();
        if (kt + 1 < ntiles) {
            issue_kv((kt + 1) & 1, n0 + AN);
            asm volatile("cp.async.commit_group;");
        }
        const float* Ks = sm + (kt & 1) * 2 * KVSTG;
        const float* Vs = Ks + KVSTG;
        const uint32_t ks_u32 = smem_u32(Ks);

        // ---- S = Q K^T (K frags via ldmatrix, swizzle in address) ----
        float s[8][4];
#pragma unroll
        for (int nj = 0; nj < 8; nj++)
#pragma unroll
            for (int r = 0; r < 4; r++) s[nj][r] = 0.0f;
#pragma unroll
        for (int kdp = 0; kdp < 4; kdp++) {
            const int kd = 2 * kdp;
            const uint32_t uoff = (uint32_t)(((4 * kdp + midx) ^ rl) << 4);
#pragma unroll
            for (int nj = 0; nj < 8; nj++) {
                uint32_t b0, b1, b2, b3;
                ldsm4(b0, b1, b2, b3,
                      ks_u32 + (uint32_t)((nj * 8 + rl) * 256) + uoff);
                mma_tf32(s[nj][0], s[nj][1], s[nj][2], s[nj][3],
                         qa[kd][0], qa[kd][1], qa[kd][2], qa[kd][3], b0, b1);
                mma_tf32(s[nj][0], s[nj][1], s[nj][2], s[nj][3],
                         qa[kd + 1][0], qa[kd + 1][1], qa[kd + 1][2], qa[kd + 1][3],
                         b2, b3);
            }
        }

        // ---- causal mask ----
        const int row0 = m0 + wrow + g;
        const int row1 = row0 + 8;
        if (n0 + AN - 1 > m0 + wrow) {
#pragma unroll
            for (int nj = 0; nj < 8; nj++) {
                int col = n0 + nj * 8 + 2 * t;
                if (col     > row0) s[nj][0] = -1e30f;
                if (col + 1 > row0) s[nj][1] = -1e30f;
                if (col     > row1) s[nj][2] = -1e30f;
                if (col + 1 > row1) s[nj][3] = -1e30f;
            }
        }

        // ---- online softmax (2 rows per thread) ----
        float rm0 = -1e30f, rm1 = -1e30f;
#pragma unroll
        for (int nj = 0; nj < 8; nj++) {
            rm0 = fmaxf(rm0, fmaxf(s[nj][0], s[nj][1]));
            rm1 = fmaxf(rm1, fmaxf(s[nj][2], s[nj][3]));
        }
        rm0 = fmaxf(rm0, __shfl_xor_sync(0xffffffffu, rm0, 1));
        rm0 = fmaxf(rm0, __shfl_xor_sync(0xffffffffu, rm0, 2));
        rm1 = fmaxf(rm1, __shfl_xor_sync(0xffffffffu, rm1, 1));
        rm1 = fmaxf(rm1, __shfl_xor_sync(0xffffffffu, rm1, 2));
        float nm0 = fmaxf(mx0, rm0), nm1 = fmaxf(mx1, rm1);
        float al0 = __expf(mx0 - nm0), al1 = __expf(mx1 - nm1);
        mx0 = nm0; mx1 = nm1;

        float rs0 = 0.0f, rs1 = 0.0f;
#pragma unroll
        for (int nj = 0; nj < 8; nj++) {
            float p0 = __expf(s[nj][0] - nm0);
            float p1 = __expf(s[nj][1] - nm0);
            float p2 = __expf(s[nj][2] - nm1);
            float p3 = __expf(s[nj][3] - nm1);
            rs0 += p0 + p1; rs1 += p2 + p3;
            *(uint2*)(Pb + (wrow + g) * ASTR + nj * 8 + 2 * t) =
                make_uint2(f2tf32(p0), f2tf32(p1));
            *(uint2*)(Pb + (wrow + g + 8) * ASTR + nj * 8 + 2 * t) =
                make_uint2(f2tf32(p2), f2tf32(p3));
        }
        rs0 += __shfl_xor_sync(0xffffffffu, rs0, 1);
        rs0 += __shfl_xor_sync(0xffffffffu, rs0, 2);
        rs1 += __shfl_xor_sync(0xffffffffu, rs1, 1);
        rs1 += __shfl_xor_sync(0xffffffffu, rs1, 2);
        l0 = l0 * al0 + rs0;
        l1 = l1 * al1 + rs1;
#pragma unroll
        for (int nj = 0; nj < 8; nj++) {
            o[nj][0] *= al0; o[nj][1] *= al0;
            o[nj][2] *= al1; o[nj][3] *= al1;
        }
        __syncwarp();

        // ---- O += P V (raw tf32 bits) ----
#pragma unroll
        for (int kp = 0; kp < 8; kp++) {
            uint32_t pa0 = __float_as_uint(Pb[(wrow + g) * ASTR + kp * 8 + t]);
            uint32_t pa1 = __float_as_uint(Pb[(wrow + g + 8) * ASTR + kp * 8 + t]);
            uint32_t pa2 = __float_as_uint(Pb[(wrow + g) * ASTR + kp * 8 + t + 4]);
            uint32_t pa3 = __float_as_uint(Pb[(wrow + g + 8) * ASTR + kp * 8 + t + 4]);
#pragma unroll
            for (int nj = 0; nj < 8; nj++) {
                const float* vr0 = Vs + (kp * 8 + t) * 64;
                const float* vr1 = Vs + (kp * 8 + t + 4) * 64;
                int c4 = 2 * nj + (g >> 2);
                uint32_t b0 = __float_as_uint(vr0[(c4 ^ t) * 4 + (g & 3)]);
                uint32_t b1 = __float_as_uint(vr1[(c4 ^ (t + 4)) * 4 + (g & 3)]);
                mma_tf32(o[nj][0], o[nj][1], o[nj][2], o[nj][3],
                         pa0, pa1, pa2, pa3, b0, b1);
            }
        }
        __syncwarp();
    }

    // ---- normalize + write (tf32-rounded for the proj GEMM) ----
    const float i0 = 1.0f / l0, i1 = 1.0f / l1;
    const int row0 = m0 + wrow + g;
    float* ob0 = ao + ((size_t)(b * TSEQ + row0)) * CDIM + h * HD;
    float* ob1 = ob0 + 8 * CDIM;
#pragma unroll
    for (int nj = 0; nj < 8; nj++) {
        *(float2*)(ob0 + nj * 8 + 2 * t) =
            make_float2(rtf(o[nj][0] * i0), rtf(o[nj][1] * i0));
        *(float2*)(ob1 + nj * 8 + 2 * t) =
            make_float2(rtf(o[nj][2] * i1), rtf(o[nj][3] * i1));
    }
}

// ---------------------------------------------------------------------------
// Host launcher
// ---------------------------------------------------------------------------
extern "C" void kernel_launch(void* const* d_in, const int* in_sizes, int n_in,
                              void* d_out, int out_size)
{
    const float* x       = (const float*)d_in[0];  // [2,2048,1024]
    const float* f_cos   = (const float*)d_in[1];  // [2048,32]
    const float* f_sin   = (const float*)d_in[2];  // [2048,32]
    const float* qkv_w   = (const float*)d_in[3];  // [3072,1024]
    const float* proj_w  = (const float*)d_in[4];  // [1024,1024]
    float* out = (float*)d_out;

    float *qkv_ptr, *ao_ptr, *xr_ptr, *wq_ptr, *wp_ptr;
    cudaGetSymbolAddress((void**)&qkv_ptr, g_qkv);
    cudaGetSymbolAddress((void**)&ao_ptr,  g_ao);
    cudaGetSymbolAddress((void**)&xr_ptr,  g_xr);
    cudaGetSymbolAddress((void**)&wq_ptr,  g_wq);
    cudaGetSymbolAddress((void**)&wp_ptr,  g_wp);

    cudaFuncSetAttribute(gemm_tf32_nt,
                         cudaFuncAttributeMaxDynamicSharedMemorySize, GEMM_SMEM);
    cudaFuncSetAttribute(attn_mma,
                         cudaFuncAttributeMaxDynamicSharedMemorySize, ATTN_SMEM);

    // 0) Pre-round x and weights to tf32
    round_tf32_kernel<<<1024, 256>>>((const float4*)x, (float4*)xr_ptr,
                                     BT * CDIM / 4);
    round_tf32_kernel<<<1024, 256>>>((const float4*)qkv_w, (float4*)wq_ptr,
                                     QKVDIM * CDIM / 4);
    round_tf32_kernel<<<1024, 256>>>((const float4*)proj_w, (float4*)wp_ptr,
                                     CDIM * CDIM / 4);

    // 1) QKV projection
    {
        dim3 grid(QKVDIM / TN, BT / TM);
        gemm_tf32_nt<<<grid, 256, GEMM_SMEM>>>(xr_ptr, wq_ptr, qkv_ptr,
                                               BT, QKVDIM, CDIM);
    }

    // 2) RoPE (+ tf32 rounding of q,k,v)
    rope_kernel<<<2048, 256>>>(qkv_ptr, f_cos, f_sin);

    // 3) Causal flash attention
    {
        dim3 grid(TSEQ / AM, HEADS, BATCH);
        attn_mma<<<grid, 256, ATTN_SMEM>>>(qkv_ptr, ao_ptr);
    }

    // 4) Output projection
    {
        dim3 grid(CDIM / TN, BT / TM);
        gemm_tf32_nt<<<grid, 256, GEMM_SMEM>>>(ao_ptr, wp_ptr, out,
                                               BT, CDIM, CDIM);
    }
}

// round 13
// speedup vs baseline: 4.4954x; 1.0105x over previous
#include <cuda_runtime.h>
#include <cstdint>
#include <math.h>

// Problem constants
#define BATCH   2
#define TSEQ    2048
#define CDIM    1024
#define HEADS   16
#define HD      64
#define BT      (BATCH * TSEQ)          // 4096 rows
#define QKVDIM  (3 * CDIM)              // 3072

// Scratch (allocation-free rule: __device__ globals)
__device__ float g_qkv[(size_t)BT * QKVDIM];    // [4096, 3072]
__device__ float g_ao [(size_t)BT * CDIM];      // [4096, 1024] (tf32-rounded)
__device__ float g_xr [(size_t)BT * CDIM];      // x, tf32-rounded
__device__ float g_wq [(size_t)QKVDIM * CDIM];  // qkv_w, tf32-rounded
__device__ float g_wp [(size_t)CDIM * CDIM];    // proj_w, tf32-rounded

__device__ __forceinline__ uint32_t f2tf32(float v) {
    uint32_t u;
    asm("cvt.rna.tf32.f32 %0, %1;" : "=r"(u) : "f"(v));
    return u;
}
__device__ __forceinline__ float rtf(float v) {
    return __uint_as_float(f2tf32(v));
}
__device__ __forceinline__ uint32_t smem_u32(const void* p) {
    uint32_t a;
    asm("{ .reg .u64 t; cvta.to.shared.u64 t, %1; cvt.u32.u64 %0, t; }"
        : "=r"(a) : "l"(p));
    return a;
}
__device__ __forceinline__ void cp_async16(uint32_t dst, const void* src) {
    asm volatile("cp.async.cg.shared.global [%0], [%1], 16;"
                 :: "r"(dst), "l"(src));
}
__device__ __forceinline__ void ldsm4(uint32_t& r0, uint32_t& r1,
                                      uint32_t& r2, uint32_t& r3, uint32_t addr) {
    asm volatile("ldmatrix.sync.aligned.m8n8.x4.shared.b16 {%0,%1,%2,%3}, [%4];"
                 : "=r"(r0), "=r"(r1), "=r"(r2), "=r"(r3) : "r"(addr));
}

__device__ __forceinline__ void mma_tf32(
    float& c0, float& c1, float& c2, float& c3,
    uint32_t a0, uint32_t a1, uint32_t a2, uint32_t a3,
    uint32_t b0, uint32_t b1)
{
    asm volatile(
        "mma.sync.aligned.m16n8k8.row.col.f32.tf32.tf32.f32 "
        "{%0,%1,%2,%3}, {%4,%5,%6,%7}, {%8,%9}, {%0,%1,%2,%3};"
        : "+f"(c0), "+f"(c1), "+f"(c2), "+f"(c3)
        : "r"(a0), "r"(a1), "r"(a2), "r"(a3), "r"(b0), "r"(b1));
}

// ---------------------------------------------------------------------------
// Pre-round pass: dst[i] = tf32_rna(src[i])
// ---------------------------------------------------------------------------
__global__ __launch_bounds__(256) void round_tf32_kernel(
    const float4* __restrict__ src, float4* __restrict__ dst, int n4)
{
    for (int i = blockIdx.x * blockDim.x + threadIdx.x; i < n4;
         i += gridDim.x * blockDim.x) {
        float4 v = src[i];
        dst[i] = make_float4(rtf(v.x), rtf(v.y), rtf(v.z), rtf(v.w));
    }
}

// ---------------------------------------------------------------------------
// TF32 mma.sync GEMM, 3-stage cp.async pipeline, ldmatrix fragment loads.
// MODE 0: plain epilogue (raw fp32 stores) — proj GEMM.
// MODE 1: fused RoPE epilogue — rotate q/k pairs, tf32-round q/k/v — QKV GEMM.
// C[M,N] = A[M,K] @ B[N,K]^T. 128x128 CTA tile, BK=32, 8 warps (4Mx2N).
// ---------------------------------------------------------------------------
#define TM  128
#define TN  128
#define BKF 32
#define SSTR 36
#define STG (TM * SSTR)                  // floats per matrix per stage (4608)
#define NSTAGE 3
#define GEMM_SMEM (NSTAGE * 2 * STG * 4) // 110592 bytes

template <int MODE>
__global__ __launch_bounds__(256, 2) void gemm_tf32_nt(
    const float* __restrict__ A, const float* __restrict__ B,
    float* __restrict__ C, int M, int N, int K,
    const float* __restrict__ cs, const float* __restrict__ sn)
{
    extern __shared__ __align__(16) float smf[];

    const int tid  = threadIdx.x;
    const int wid  = tid >> 5;
    const int lane = tid & 31;
    const int g = lane >> 2;
    const int t = lane & 3;
    const int wm = (wid & 3) * 32;
    const int wn = (wid >> 2) * 64;
    const int m0 = blockIdx.y * TM;
    const int n0 = blockIdx.x * TN;

    const int lrow = tid >> 3;
    const int lq   = (tid & 7) * 4;

    const int aoff0 = (wm + (lane & 15)) * SSTR + ((lane & 16) >> 2);
    const int boff0 = (wn + ((lane & 16) >> 1) + (lane & 7)) * SSTR
                    + ((lane & 8) >> 1);

    float c[2][8][4];
#pragma unroll
    for (int mi = 0; mi < 2; mi++)
#pragma unroll
        for (int ni = 0; ni < 8; ni++)
#pragma unroll
            for (int r = 0; r < 4; r++) c[mi][ni][r] = 0.0f;

    const int nch = K / BKF;

    auto issue_load = [&](int s, int k0) {
        float* As = smf + s * 2 * STG;
        float* Bs = As + STG;
#pragma unroll
        for (int i = 0; i < 4; i++) {
            int row = lrow + i * 32;
            cp_async16(smem_u32(As + row * SSTR + lq),
                       A + (size_t)(m0 + row) * K + k0 + lq);
            cp_async16(smem_u32(Bs + row * SSTR + lq),
                       B + (size_t)(n0 + row) * K + k0 + lq);
        }
    };

    issue_load(0, 0);
    asm volatile("cp.async.commit_group;");
    if (nch > 1) issue_load(1, BKF);
    asm volatile("cp.async.commit_group;");

    for (int cch = 0; cch < nch; cch++) {
        asm volatile("cp.async.wait_group 1;");
        __syncthreads();
        if (cch + 2 < nch) issue_load((cch + 2) % NSTAGE, (cch + 2) * BKF);
        asm volatile("cp.async.commit_group;");

        const float* As = smf + (cch % NSTAGE) * 2 * STG;
        const float* Bs = As + STG;
        const uint32_t a_base = smem_u32(As) + aoff0 * 4;
        const uint32_t b_base = smem_u32(Bs) + boff0 * 4;

#pragma unroll
        for (int kk = 0; kk < 4; kk++) {
            const int kb = kk * 8;
            uint32_t a[2][4];
#pragma unroll
            for (int mi = 0; mi < 2; mi++)
                ldsm4(a[mi][0], a[mi][1], a[mi][2], a[mi][3],
                      a_base + (mi * 16 * SSTR + kb) * 4);
            uint32_t b[8][2];
#pragma unroll
            for (int p = 0; p < 4; p++)
                ldsm4(b[2 * p][0], b[2 * p][1], b[2 * p + 1][0], b[2 * p + 1][1],
                      b_base + (p * 16 * SSTR + kb) * 4);
#pragma unroll
            for (int mi = 0; mi < 2; mi++)
#pragma unroll
                for (int ni = 0; ni < 8; ni++)
                    mma_tf32(c[mi][ni][0], c[mi][ni][1], c[mi][ni][2], c[mi][ni][3],
                             a[mi][0], a[mi][1], a[mi][2], a[mi][3],
                             b[ni][0], b[ni][1]);
        }
    }

#pragma unroll
    for (int mi = 0; mi < 2; mi++) {
        const int row = m0 + wm + mi * 16 + g;
#pragma unroll
        for (int ni = 0; ni < 8; ni++) {
            const int col = n0 + wn + ni * 8 + 2 * t;
            float v0 = c[mi][ni][0], v1 = c[mi][ni][1];
            float v2 = c[mi][ni][2], v3 = c[mi][ni][3];
            if (MODE == 1) {
                if (col < 2 * CDIM) {   // q or k region: rotate pair
                    const int i  = (col & 63) >> 1;
                    const int t0 = row & (TSEQ - 1);
                    const int t1 = (row + 8) & (TSEQ - 1);
                    float c0v = __ldg(cs + t0 * 32 + i);
                    float s0v = __ldg(sn + t0 * 32 + i);
                    float c1v = __ldg(cs + t1 * 32 + i);
                    float s1v = __ldg(sn + t1 * 32 + i);
                    float r0 = v0 * c0v - v1 * s0v;
                    float r1 = v0 * s0v + v1 * c0v;
                    float r2 = v2 * c1v - v3 * s1v;
                    float r3 = v2 * s1v + v3 * c1v;
                    v0 = r0; v1 = r1; v2 = r2; v3 = r3;
                }
                v0 = rtf(v0); v1 = rtf(v1); v2 = rtf(v2); v3 = rtf(v3);
            }
            *(float2*)(C + (size_t)row * N + col) = make_float2(v0, v1);
            *(float2*)(C + (size_t)(row + 8) * N + col) = make_float2(v2, v3);
        }
    }
}

// ---------------------------------------------------------------------------
// Flash attention, tf32 mma.sync, double-buffered cp.async K/V staging,
// ldmatrix K-fragment loads. exp2-based softmax (log2e folded into Q scale).
// ---------------------------------------------------------------------------
#define AM 128
#define AN 64
#define ASTR 68
#define KVSTG (AN * 64)              // floats per K or V stage (4096)
#define ATTN_SMEM ((4 * KVSTG + AM * ASTR) * 4)   // 100,352 bytes
#define QSCALE 0.1803368801111204f   // 0.125 * log2(e)

__global__ __launch_bounds__(256, 2) void attn_mma(
    const float* __restrict__ qkv, float* __restrict__ ao)
{
    extern __shared__ __align__(16) float sm[];
    float* Pb = sm + 4 * KVSTG;         // [128][68]

    const int m0 = (gridDim.x - 1 - blockIdx.x) * AM;
    const int h  = blockIdx.y;
    const int b  = blockIdx.z;
    const int tid = threadIdx.x;
    const int wid = tid >> 5, lane = tid & 31;
    const int g = lane >> 2, t = lane & 3;
    const int wrow = wid * 16;
    const int rl = lane & 7, midx = lane >> 3;

    const float* kvb = qkv + (size_t)b * TSEQ * QKVDIM + CDIM + h * HD;

    auto issue_kv = [&](int s, int n0) {
        float* Ks = sm + s * 2 * KVSTG;
        float* Vs = Ks + KVSTG;
        const float* kb = kvb + (size_t)n0 * QKVDIM;
        const float* vb = kb + CDIM;
#pragma unroll
        for (int i = 0; i < 4; i++) {
            int e   = tid + i * 256;
            int row = e >> 4;
            int u   = e & 15;
            int u2  = u ^ (row & 7);
            cp_async16(smem_u32(Ks + row * 64 + u2 * 4),
                       kb + (size_t)row * QKVDIM + u * 4);
            cp_async16(smem_u32(Vs + row * 64 + u2 * 4),
                       vb + (size_t)row * QKVDIM + u * 4);
        }
    };

    const int ntiles = (m0 + AM) / AN;
    issue_kv(0, 0);
    asm volatile("cp.async.commit_group;");

    // ---- Stage Q (x QSCALE, re-rounded to tf32) into Pb ----
    const float* qbase = qkv + ((size_t)(b * TSEQ + m0)) * QKVDIM + h * HD;
    for (int e = tid; e < AM * 16; e += 256) {
        int r = e >> 4, c4 = (e & 15) * 4;
        float4 v = *(const float4*)(qbase + (size_t)r * QKVDIM + c4);
        *(float4*)(Pb + r * ASTR + c4) = make_float4(
            rtf(v.x * QSCALE), rtf(v.y * QSCALE),
            rtf(v.z * QSCALE), rtf(v.w * QSCALE));
    }
    __syncthreads();
    uint32_t qa[8][4];
#pragma unroll
    for (int kd = 0; kd < 8; kd++) {
        qa[kd][0] = __float_as_uint(Pb[(wrow + g) * ASTR + kd * 8 + t]);
        qa[kd][1] = __float_as_uint(Pb[(wrow + g + 8) * ASTR + kd * 8 + t]);
        qa[kd][2] = __float_as_uint(Pb[(wrow + g) * ASTR + kd * 8 + t + 4]);
        qa[kd][3] = __float_as_uint(Pb[(wrow + g + 8) * ASTR + kd * 8 + t + 4]);
    }

    float o[8][4];
#pragma unroll
    for (int nj = 0; nj < 8; nj++)
#pragma unroll
        for (int r = 0; r < 4; r++) o[nj][r] = 0.0f;
    float mx0 = -1e30f, mx1 = -1e30f, l0 = 0.0f, l1 = 0.0f;

    for (int kt = 0; kt < ntiles; kt++) {
        const int n0 = kt * AN;
        asm volatile("cp.async.wait_group 0;");
        __syncthreads();
        if (kt + 1 < ntiles) {
            issue_kv((kt + 1) & 1, n0 + AN);
            asm volatile("cp.async.commit_group;");
        }
        const float* Ks = sm + (kt & 1) * 2 * KVSTG;
        const float* Vs = Ks + KVSTG;
        const uint32_t ks_u32 = smem_u32(Ks);

        // ---- S = Q K^T (log2-domain scores) ----
        float s[8][4];
#pragma unroll
        for (int nj = 0; nj < 8; nj++)
#pragma unroll
            for (int r = 0; r < 4; r++) s[nj][r] = 0.0f;
#pragma unroll
        for (int kdp = 0; kdp < 4; kdp++) {
            const int kd = 2 * kdp;
            const uint32_t uoff = (uint32_t)(((4 * kdp + midx) ^ rl) << 4);
#pragma unroll
            for (int nj = 0; nj < 8; nj++) {
                uint32_t b0, b1, b2, b3;
                ldsm4(b0, b1, b2, b3,
                      ks_u32 + (uint32_t)((nj * 8 + rl) * 256) + uoff);
                mma_tf32(s[nj][0], s[nj][1], s[nj][2], s[nj][3],
                         qa[kd][0], qa[kd][1], qa[kd][2], qa[kd][3], b0, b1);
                mma_tf32(s[nj][0], s[nj][1], s[nj][2], s[nj][3],
                         qa[kd + 1][0], qa[kd + 1][1], qa[kd + 1][2], qa[kd + 1][3],
                         b2, b3);
            }
        }

        // ---- causal mask ----
        const int row0 = m0 + wrow + g;
        const int row1 = row0 + 8;
        if (n0 + AN - 1 > m0 + wrow) {
#pragma unroll
            for (int nj = 0; nj < 8; nj++) {
                int col = n0 + nj * 8 + 2 * t;
                if (col     > row0) s[nj][0] = -1e30f;
                if (col + 1 > row0) s[nj][1] = -1e30f;
                if (col     > row1) s[nj][2] = -1e30f;
                if (col + 1 > row1) s[nj][3] = -1e30f;
            }
        }

        // ---- online softmax (base-2, 2 rows per thread) ----
        float rm0 = -1e30f, rm1 = -1e30f;
#pragma unroll
        for (int nj = 0; nj < 8; nj++) {
            rm0 = fmaxf(rm0, fmaxf(s[nj][0], s[nj][1]));
            rm1 = fmaxf(rm1, fmaxf(s[nj][2], s[nj][3]));
        }
        rm0 = fmaxf(rm0, __shfl_xor_sync(0xffffffffu, rm0, 1));
        rm0 = fmaxf(rm0, __shfl_xor_sync(0xffffffffu, rm0, 2));
        rm1 = fmaxf(rm1, __shfl_xor_sync(0xffffffffu, rm1, 1));
        rm1 = fmaxf(rm1, __shfl_xor_sync(0xffffffffu, rm1, 2));
        float nm0 = fmaxf(mx0, rm0), nm1 = fmaxf(mx1, rm1);
        float al0 = exp2f(mx0 - nm0), al1 = exp2f(mx1 - nm1);
        mx0 = nm0; mx1 = nm1;

        float rs0 = 0.0f, rs1 = 0.0f;
#pragma unroll
        for (int nj = 0; nj < 8; nj++) {
            float p0 = exp2f(s[nj][0] - nm0);
            float p1 = exp2f(s[nj][1] - nm0);
            float p2 = exp2f(s[nj][2] - nm1);
            float p3 = exp2f(s[nj][3] - nm1);
            rs0 += p0 + p1; rs1 += p2 + p3;
            *(uint2*)(Pb + (wrow + g) * ASTR + nj * 8 + 2 * t) =
                make_uint2(f2tf32(p0), f2tf32(p1));
            *(uint2*)(Pb + (wrow + g + 8) * ASTR + nj * 8 + 2 * t) =
                make_uint2(f2tf32(p2), f2tf32(p3));
        }
        rs0 += __shfl_xor_sync(0xffffffffu, rs0, 1);
        rs0 += __shfl_xor_sync(0xffffffffu, rs0, 2);
        rs1 += __shfl_xor_sync(0xffffffffu, rs1, 1);
        rs1 += __shfl_xor_sync(0xffffffffu, rs1, 2);
        l0 = l0 * al0 + rs0;
        l1 = l1 * al1 + rs1;
#pragma unroll
        for (int nj = 0; nj < 8; nj++) {
            o[nj][0] *= al0; o[nj][1] *= al0;
            o[nj][2] *= al1; o[nj][3] *= al1;
        }
        __syncwarp();

        // ---- O += P V ----
#pragma unroll
        for (int kp = 0; kp < 8; kp++) {
            uint32_t pa0 = __float_as_uint(Pb[(wrow + g) * ASTR + kp * 8 + t]);
            uint32_t pa1 = __float_as_uint(Pb[(wrow + g + 8) * ASTR + kp * 8 + t]);
            uint32_t pa2 = __float_as_uint(Pb[(wrow + g) * ASTR + kp * 8 + t + 4]);
            uint32_t pa3 = __float_as_uint(Pb[(wrow + g + 8) * ASTR + kp * 8 + t + 4]);
#pragma unroll
            for (int nj = 0; nj < 8; nj++) {
                const float* vr0 = Vs + (kp * 8 + t) * 64;
                const float* vr1 = Vs + (kp * 8 + t + 4) * 64;
                int c4 = 2 * nj + (g >> 2);
                uint32_t b0 = __float_as_uint(vr0[(c4 ^ t) * 4 + (g & 3)]);
                uint32_t b1 = __float_as_uint(vr1[(c4 ^ (t + 4)) * 4 + (g & 3)]);
                mma_tf32(o[nj][0], o[nj][1], o[nj][2], o[nj][3],
                         pa0, pa1, pa2, pa3, b0, b1);
            }
        }
        __syncwarp();
    }

    // ---- normalize + write (tf32-rounded for the proj GEMM) ----
    const float i0 = 1.0f / l0, i1 = 1.0f / l1;
    const int row0 = m0 + wrow + g;
    float* ob0 = ao + ((size_t)(b * TSEQ + row0)) * CDIM + h * HD;
    float* ob1 = ob0 + 8 * CDIM;
#pragma unroll
    for (int nj = 0; nj < 8; nj++) {
        *(float2*)(ob0 + nj * 8 + 2 * t) =
            make_float2(rtf(o[nj][0] * i0), rtf(o[nj][1] * i0));
        *(float2*)(ob1 + nj * 8 + 2 * t) =
            make_float2(rtf(o[nj][2] * i1), rtf(o[nj][3] * i1));
    }
}

// ---------------------------------------------------------------------------
// Host launcher
// ---------------------------------------------------------------------------
extern "C" void kernel_launch(void* const* d_in, const int* in_sizes, int n_in,
                              void* d_out, int out_size)
{
    const float* x       = (const float*)d_in[0];  // [2,2048,1024]
    const float* f_cos   = (const float*)d_in[1];  // [2048,32]
    const float* f_sin   = (const float*)d_in[2];  // [2048,32]
    const float* qkv_w   = (const float*)d_in[3];  // [3072,1024]
    const float* proj_w  = (const float*)d_in[4];  // [1024,1024]
    float* out = (float*)d_out;

    float *qkv_ptr, *ao_ptr, *xr_ptr, *wq_ptr, *wp_ptr;
    cudaGetSymbolAddress((void**)&qkv_ptr, g_qkv);
    cudaGetSymbolAddress((void**)&ao_ptr,  g_ao);
    cudaGetSymbolAddress((void**)&xr_ptr,  g_xr);
    cudaGetSymbolAddress((void**)&wq_ptr,  g_wq);
    cudaGetSymbolAddress((void**)&wp_ptr,  g_wp);

    cudaFuncSetAttribute(gemm_tf32_nt<0>,
                         cudaFuncAttributeMaxDynamicSharedMemorySize, GEMM_SMEM);
    cudaFuncSetAttribute(gemm_tf32_nt<1>,
                         cudaFuncAttributeMaxDynamicSharedMemorySize, GEMM_SMEM);
    cudaFuncSetAttribute(attn_mma,
                         cudaFuncAttributeMaxDynamicSharedMemorySize, ATTN_SMEM);

    // 0) Pre-round x and weights to tf32
    round_tf32_kernel<<<1024, 256>>>((const float4*)x, (float4*)xr_ptr,
                                     BT * CDIM / 4);
    round_tf32_kernel<<<1024, 256>>>((const float4*)qkv_w, (float4*)wq_ptr,
                                     QKVDIM * CDIM / 4);
    round_tf32_kernel<<<1024, 256>>>((const float4*)proj_w, (float4*)wp_ptr,
                                     CDIM * CDIM / 4);

    // 1) QKV projection with fused RoPE + tf32-rounding epilogue
    {
        dim3 grid(QKVDIM / TN, BT / TM);
        gemm_tf32_nt<1><<<grid, 256, GEMM_SMEM>>>(xr_ptr, wq_ptr, qkv_ptr,
                                                  BT, QKVDIM, CDIM,
                                                  f_cos, f_sin);
    }

    // 2) Causal flash attention (exp2 softmax)
    {
        dim3 grid(TSEQ / AM, HEADS, BATCH);
        attn_mma<<<grid, 256, ATTN_SMEM>>>(qkv_ptr, ao_ptr);
    }

    // 3) Output projection (plain epilogue)
    {
        dim3 grid(CDIM / TN, BT / TM);
        gemm_tf32_nt<0><<<grid, 256, GEMM_SMEM>>>(ao_ptr, wp_ptr, out,
                                                  BT, CDIM, CDIM,
                                                  nullptr, nullptr);
    }
}

// round 14
// speedup vs baseline: 8.3105x; 1.8487x over previous
#include <cuda_runtime.h>
#include <cuda_fp16.h>
#include <cstdint>
#include <math.h>

// Problem constants
#define BATCH   2
#define TSEQ    2048
#define CDIM    1024
#define HEADS   16
#define HD      64
#define BT      (BATCH * TSEQ)          // 4096 rows
#define QKVDIM  (3 * CDIM)              // 3072

// Scratch (allocation-free rule: __device__ globals) — all fp16 now
__device__ __half g_qkv[(size_t)BT * QKVDIM];    // q(scaled,roped) k(roped) v
__device__ __half g_ao [(size_t)BT * CDIM];      // attention output
__device__ __half g_xr [(size_t)BT * CDIM];      // x, fp16
__device__ __half g_wq [(size_t)QKVDIM * CDIM];  // qkv_w, fp16
__device__ __half g_wp [(size_t)CDIM * CDIM];    // proj_w, fp16

#define QSCALE 0.1803368801111204f   // 0.125 * log2(e)

__device__ __forceinline__ uint32_t smem_u32(const void* p) {
    uint32_t a;
    asm("{ .reg .u64 t; cvta.to.shared.u64 t, %1; cvt.u32.u64 %0, t; }"
        : "=r"(a) : "l"(p));
    return a;
}
__device__ __forceinline__ void cp_async16(uint32_t dst, const void* src) {
    asm volatile("cp.async.cg.shared.global [%0], [%1], 16;"
                 :: "r"(dst), "l"(src));
}
__device__ __forceinline__ void ldsm4(uint32_t& r0, uint32_t& r1,
                                      uint32_t& r2, uint32_t& r3, uint32_t addr) {
    asm volatile("ldmatrix.sync.aligned.m8n8.x4.shared.b16 {%0,%1,%2,%3}, [%4];"
                 : "=r"(r0), "=r"(r1), "=r"(r2), "=r"(r3) : "r"(addr));
}
__device__ __forceinline__ void ldsm4t(uint32_t& r0, uint32_t& r1,
                                       uint32_t& r2, uint32_t& r3, uint32_t addr) {
    asm volatile("ldmatrix.sync.aligned.m8n8.x4.trans.shared.b16 {%0,%1,%2,%3}, [%4];"
                 : "=r"(r0), "=r"(r1), "=r"(r2), "=r"(r3) : "r"(addr));
}
// m16n8k16 fp16 -> fp32 accumulate
__device__ __forceinline__ void mma_f16(
    float& c0, float& c1, float& c2, float& c3,
    uint32_t a0, uint32_t a1, uint32_t a2, uint32_t a3,
    uint32_t b0, uint32_t b1)
{
    asm volatile(
        "mma.sync.aligned.m16n8k16.row.col.f32.f16.f16.f32 "
        "{%0,%1,%2,%3}, {%4,%5,%6,%7}, {%8,%9}, {%0,%1,%2,%3};"
        : "+f"(c0), "+f"(c1), "+f"(c2), "+f"(c3)
        : "r"(a0), "r"(a1), "r"(a2), "r"(a3), "r"(b0), "r"(b1));
}

// ---------------------------------------------------------------------------
// Pre-convert pass: fp32 -> fp16
// ---------------------------------------------------------------------------
__global__ __launch_bounds__(256) void to_fp16_kernel(
    const float4* __restrict__ src, __half2* __restrict__ dst, int n4)
{
    for (int i = blockIdx.x * blockDim.x + threadIdx.x; i < n4;
         i += gridDim.x * blockDim.x) {
        float4 v = src[i];
        dst[2 * i]     = __floats2half2_rn(v.x, v.y);
        dst[2 * i + 1] = __floats2half2_rn(v.z, v.w);
    }
}

// ---------------------------------------------------------------------------
// FP16 mma.sync GEMM, 3-stage cp.async pipeline, ldmatrix fragments.
// MODE 0: plain fp32-store epilogue (proj GEMM, C = float*).
// MODE 1: fused RoPE epilogue, fp16 stores (QKV GEMM, C = half*);
//         q third additionally scaled by QSCALE.
// C[M,N] = A[M,K] @ B[N,K]^T. 128x128 CTA tile, BK=32, 8 warps (4Mx2N).
// ---------------------------------------------------------------------------
#define TM  128
#define TN  128
#define BKF 32
#define SSTRH 40                         // halves; stride keeps ldsm conflict-free
#define STGH (TM * SSTRH)                // halves per matrix stage (5120)
#define NSTAGE 3
#define GEMM_SMEM (NSTAGE * 2 * STGH * 2)   // 61440 bytes

template <int MODE>
__global__ __launch_bounds__(256, 2) void gemm_f16_nt(
    const __half* __restrict__ A, const __half* __restrict__ B,
    void* __restrict__ Cv, int M, int N, int K,
    const float* __restrict__ cs, const float* __restrict__ sn)
{
    extern __shared__ __align__(16) __half smh[];

    const int tid  = threadIdx.x;
    const int wid  = tid >> 5;
    const int lane = tid & 31;
    const int g = lane >> 2;
    const int t = lane & 3;
    const int rl = lane & 7;
    const int wm = (wid & 3) * 32;
    const int wn = (wid >> 2) * 64;
    const int m0 = blockIdx.y * TM;
    const int n0 = blockIdx.x * TN;

    // ldmatrix lane-row decomposition
    const int a_row = wm + rl + ((lane & 8) ? 8 : 0);     // + mi*16
    const int a_k   = (lane & 16) ? 8 : 0;                // + ks
    const int b_row = wn + rl + ((lane & 16) ? 8 : 0);    // + p*16
    const int b_k   = (lane & 8) ? 8 : 0;                 // + ks

    float c[2][8][4];
#pragma unroll
    for (int mi = 0; mi < 2; mi++)
#pragma unroll
        for (int ni = 0; ni < 8; ni++)
#pragma unroll
            for (int r = 0; r < 4; r++) c[mi][ni][r] = 0.0f;

    const int nch = K / BKF;

    auto issue_load = [&](int s, int k0) {
        __half* As = smh + s * 2 * STGH;
        __half* Bs = As + STGH;
#pragma unroll
        for (int i = 0; i < 2; i++) {
            int e   = tid + i * 256;      // 0..511
            int row = e >> 2;
            int u   = (e & 3) * 8;        // halves
            cp_async16(smem_u32(As + row * SSTRH + u),
                       A + (size_t)(m0 + row) * K + k0 + u);
            cp_async16(smem_u32(Bs + row * SSTRH + u),
                       B + (size_t)(n0 + row) * K + k0 + u);
        }
    };

    issue_load(0, 0);
    asm volatile("cp.async.commit_group;");
    if (nch > 1) issue_load(1, BKF);
    asm volatile("cp.async.commit_group;");

    for (int cch = 0; cch < nch; cch++) {
        asm volatile("cp.async.wait_group 1;");
        __syncthreads();
        if (cch + 2 < nch) issue_load((cch + 2) % NSTAGE, (cch + 2) * BKF);
        asm volatile("cp.async.commit_group;");

        const __half* As = smh + (cch % NSTAGE) * 2 * STGH;
        const __half* Bs = As + STGH;
        const uint32_t a_base = smem_u32(As) + (uint32_t)((a_row * SSTRH + a_k) * 2);
        const uint32_t b_base = smem_u32(Bs) + (uint32_t)((b_row * SSTRH + b_k) * 2);

#pragma unroll
        for (int ks8 = 0; ks8 < 2; ks8++) {
            const uint32_t ko = (uint32_t)(ks8 * 16 * 2);   // bytes
            uint32_t a[2][4];
#pragma unroll
            for (int mi = 0; mi < 2; mi++)
                ldsm4(a[mi][0], a[mi][1], a[mi][2], a[mi][3],
                      a_base + (uint32_t)(mi * 16 * SSTRH * 2) + ko);
            uint32_t b[8][2];
#pragma unroll
            for (int p = 0; p < 4; p++)
                ldsm4(b[2 * p][0], b[2 * p][1], b[2 * p + 1][0], b[2 * p + 1][1],
                      b_base + (uint32_t)(p * 16 * SSTRH * 2) + ko);
#pragma unroll
            for (int mi = 0; mi < 2; mi++)
#pragma unroll
                for (int ni = 0; ni < 8; ni++)
                    mma_f16(c[mi][ni][0], c[mi][ni][1], c[mi][ni][2], c[mi][ni][3],
                            a[mi][0], a[mi][1], a[mi][2], a[mi][3],
                            b[ni][0], b[ni][1]);
        }
    }

#pragma unroll
    for (int mi = 0; mi < 2; mi++) {
        const int row = m0 + wm + mi * 16 + g;
#pragma unroll
        for (int ni = 0; ni < 8; ni++) {
            const int col = n0 + wn + ni * 8 + 2 * t;
            float v0 = c[mi][ni][0], v1 = c[mi][ni][1];
            float v2 = c[mi][ni][2], v3 = c[mi][ni][3];
            if (MODE == 1) {
                if (col < 2 * CDIM) {     // q or k region: rotate pair
                    const int i  = (col & 63) >> 1;
                    const int t0 = row & (TSEQ - 1);
                    const int t1 = (row + 8) & (TSEQ - 1);
                    float c0v = __ldg(cs + t0 * 32 + i);
                    float s0v = __ldg(sn + t0 * 32 + i);
                    float c1v = __ldg(cs + t1 * 32 + i);
                    float s1v = __ldg(sn + t1 * 32 + i);
                    float r0 = v0 * c0v - v1 * s0v;
                    float r1 = v0 * s0v + v1 * c0v;
                    float r2 = v2 * c1v - v3 * s1v;
                    float r3 = v2 * s1v + v3 * c1v;
                    if (col < CDIM) {     // q: fold softmax scale
                        r0 *= QSCALE; r1 *= QSCALE; r2 *= QSCALE; r3 *= QSCALE;
                    }
                    v0 = r0; v1 = r1; v2 = r2; v3 = r3;
                }
                __half* Ch = (__half*)Cv;
                *(__half2*)(Ch + (size_t)row * N + col) = __floats2half2_rn(v0, v1);
                *(__half2*)(Ch + (size_t)(row + 8) * N + col) = __floats2half2_rn(v2, v3);
            } else {
                float* Cf = (float*)Cv;
                *(float2*)(Cf + (size_t)row * N + col) = make_float2(v0, v1);
                *(float2*)(Cf + (size_t)(row + 8) * N + col) = make_float2(v2, v3);
            }
        }
    }
}

// ---------------------------------------------------------------------------
// Flash attention, fp16 m16n8k16. Double-buffered cp.async K/V (swizzled
// 128B rows), ldmatrix for Q/K/P and ldmatrix.trans for V. exp2 softmax
// (scale pre-folded into q). Output fp16 for the proj GEMM.
// ---------------------------------------------------------------------------
#define AM 128
#define AN 64
#define PBSTR 72                       // halves
#define KVSTGH (AN * 64)               // halves per K or V stage (4096 = 8KB)
// smem: 2 stages x (K+V) + Pb = 4*4096 + 128*72 halves = 51,200 bytes
#define ATTN_SMEM ((4 * KVSTGH + AM * PBSTR) * 2)

__global__ __launch_bounds__(256, 2) void attn_mma(
    const __half* __restrict__ qkv, __half* __restrict__ ao)
{
    extern __shared__ __align__(16) __half smA[];
    __half* Pb = smA + 4 * KVSTGH;      // [128][72] halves: Q staging, then P

    const int m0 = (gridDim.x - 1 - blockIdx.x) * AM;   // long-first
    const int h  = blockIdx.y;
    const int b  = blockIdx.z;
    const int tid = threadIdx.x;
    const int wid = tid >> 5, lane = tid & 31;
    const int g = lane >> 2, t = lane & 3;
    const int rl = lane & 7;
    const int wrow = wid * 16;

    const __half* kvb = qkv + (size_t)b * TSEQ * QKVDIM + CDIM + h * HD;

    auto issue_kv = [&](int s, int n0) {
        __half* Ks = smA + s * 2 * KVSTGH;
        __half* Vs = Ks + KVSTGH;
        const __half* kb = kvb + (size_t)n0 * QKVDIM;
        const __half* vb = kb + CDIM;
#pragma unroll
        for (int i = 0; i < 2; i++) {
            int e   = tid + i * 256;    // 0..511
            int row = e >> 3;
            int u   = e & 7;
            int u2  = u ^ (row & 7);    // 16B-unit XOR swizzle (8 units/row)
            cp_async16(smem_u32(Ks + row * 64 + u2 * 8),
                       kb + (size_t)row * QKVDIM + u * 8);
            cp_async16(smem_u32(Vs + row * 64 + u2 * 8),
                       vb + (size_t)row * QKVDIM + u * 8);
        }
    };

    const int ntiles = (m0 + AM) / AN;
    issue_kv(0, 0);
    asm volatile("cp.async.commit_group;");

    // ---- Stage Q via cp.async into Pb (already scaled + fp16) ----
    {
        const __half* qbase = qkv + ((size_t)(b * TSEQ + m0)) * QKVDIM + h * HD;
#pragma unroll
        for (int i = 0; i < 4; i++) {
            int e   = tid + i * 256;    // 0..1023
            int row = e >> 3;
            int u   = e & 7;
            cp_async16(smem_u32(Pb + row * PBSTR + u * 8),
                       qbase + (size_t)row * QKVDIM + u * 8);
        }
    }
    asm volatile("cp.async.commit_group;");
    asm volatile("cp.async.wait_group 0;");
    __syncthreads();

    // Q fragments: 4 k16-steps x 4 regs, via ldmatrix (A layout)
    const uint32_t pb_u32 = smem_u32(Pb);
    const uint32_t qrow_off =
        (uint32_t)(((wrow + rl + ((lane & 8) ? 8 : 0)) * PBSTR
                    + ((lane & 16) ? 8 : 0)) * 2);
    uint32_t qa[4][4];
#pragma unroll
    for (int ks8 = 0; ks8 < 4; ks8++)
        ldsm4(qa[ks8][0], qa[ks8][1], qa[ks8][2], qa[ks8][3],
              pb_u32 + qrow_off + (uint32_t)(ks8 * 16 * 2));

    float o[8][4];
#pragma unroll
    for (int nj = 0; nj < 8; nj++)
#pragma unroll
        for (int r = 0; r < 4; r++) o[nj][r] = 0.0f;
    float mx0 = -1e30f, mx1 = -1e30f, l0 = 0.0f, l1 = 0.0f;

    for (int kt = 0; kt < ntiles; kt++) {
        const int n0 = kt * AN;
        if (kt > 0) {
            asm volatile("cp.async.wait_group 0;");
            __syncthreads();
        }
        if (kt + 1 < ntiles) {
            issue_kv((kt + 1) & 1, n0 + AN);
            asm volatile("cp.async.commit_group;");
        }
        const __half* Ks = smA + (kt & 1) * 2 * KVSTGH;
        const __half* Vs = Ks + KVSTGH;
        const uint32_t ks_u32 = smem_u32(Ks);
        const uint32_t vs_u32 = smem_u32(Vs);

        // ---- S = Q K^T ----
        float s[8][4];
#pragma unroll
        for (int nj = 0; nj < 8; nj++)
#pragma unroll
            for (int r = 0; r < 4; r++) s[nj][r] = 0.0f;
#pragma unroll
        for (int ks8 = 0; ks8 < 4; ks8++) {
#pragma unroll
            for (int p = 0; p < 4; p++) {
                // K B-frags: rows = key idx, cols = d (contiguous) -> non-trans
                int krow = p * 16 + ((lane & 16) ? 8 : 0) + rl;
                int kunit = 2 * ks8 + ((lane & 8) ? 1 : 0);
                uint32_t kaddr = ks_u32 + (uint32_t)(krow * 128)
                               + (uint32_t)(((kunit ^ (krow & 7)) * 16));
                uint32_t b0, b1, b2, b3;
                ldsm4(b0, b1, b2, b3, kaddr);
                mma_f16(s[2 * p][0], s[2 * p][1], s[2 * p][2], s[2 * p][3],
                        qa[ks8][0], qa[ks8][1], qa[ks8][2], qa[ks8][3], b0, b1);
                mma_f16(s[2 * p + 1][0], s[2 * p + 1][1], s[2 * p + 1][2], s[2 * p + 1][3],
                        qa[ks8][0], qa[ks8][1], qa[ks8][2], qa[ks8][3], b2, b3);
            }
        }

        // ---- causal mask ----
        const int row0 = m0 + wrow + g;
        const int row1 = row0 + 8;
        if (n0 + AN - 1 > m0 + wrow) {
#pragma unroll
            for (int nj = 0; nj < 8; nj++) {
                int col = n0 + nj * 8 + 2 * t;
                if (col     > row0) s[nj][0] = -1e30f;
                if (col + 1 > row0) s[nj][1] = -1e30f;
                if (col     > row1) s[nj][2] = -1e30f;
                if (col + 1 > row1) s[nj][3] = -1e30f;
            }
        }

        // ---- online softmax (base-2) ----
        float rm0 = -1e30f, rm1 = -1e30f;
#pragma unroll
        for (int nj = 0; nj < 8; nj++) {
            rm0 = fmaxf(rm0, fmaxf(s[nj][0], s[nj][1]));
            rm1 = fmaxf(rm1, fmaxf(s[nj][2], s[nj][3]));
        }
        rm0 = fmaxf(rm0, __shfl_xor_sync(0xffffffffu, rm0, 1));
        rm0 = fmaxf(rm0, __shfl_xor_sync(0xffffffffu, rm0, 2));
        rm1 = fmaxf(rm1, __shfl_xor_sync(0xffffffffu, rm1, 1));
        rm1 = fmaxf(rm1, __shfl_xor_sync(0xffffffffu, rm1, 2));
        float nm0 = fmaxf(mx0, rm0), nm1 = fmaxf(mx1, rm1);
        float al0 = exp2f(mx0 - nm0), al1 = exp2f(mx1 - nm1);
        mx0 = nm0; mx1 = nm1;

        float rs0 = 0.0f, rs1 = 0.0f;
#pragma unroll
        for (int nj = 0; nj < 8; nj++) {
            float p0 = exp2f(s[nj][0] - nm0);
            float p1 = exp2f(s[nj][1] - nm0);
            float p2 = exp2f(s[nj][2] - nm1);
            float p3 = exp2f(s[nj][3] - nm1);
            rs0 += p0 + p1; rs1 += p2 + p3;
            *(__half2*)(Pb + (wrow + g) * PBSTR + nj * 8 + 2 * t) =
                __floats2half2_rn(p0, p1);
            *(__half2*)(Pb + (wrow + g + 8) * PBSTR + nj * 8 + 2 * t) =
                __floats2half2_rn(p2, p3);
        }
        rs0 += __shfl_xor_sync(0xffffffffu, rs0, 1);
        rs0 += __shfl_xor_sync(0xffffffffu, rs0, 2);
        rs1 += __shfl_xor_sync(0xffffffffu, rs1, 1);
        rs1 += __shfl_xor_sync(0xffffffffu, rs1, 2);
        l0 = l0 * al0 + rs0;
        l1 = l1 * al1 + rs1;
#pragma unroll
        for (int nj = 0; nj < 8; nj++) {
            o[nj][0] *= al0; o[nj][1] *= al0;
            o[nj][2] *= al1; o[nj][3] *= al1;
        }
        __syncwarp();   // P visible warp-wide (warp-private rows)

        // ---- O += P V ----
#pragma unroll
        for (int kp = 0; kp < 4; kp++) {
            uint32_t pa0, pa1, pa2, pa3;
            ldsm4(pa0, pa1, pa2, pa3,
                  pb_u32 + qrow_off + (uint32_t)(kp * 16 * 2));
#pragma unroll
            for (int p = 0; p < 4; p++) {
                // V B-frags: rows = key idx, need k-major pairs -> trans
                int vrow = kp * 16 + ((lane & 8) ? 8 : 0) + rl;
                int vunit = 2 * p + ((lane & 16) ? 1 : 0);
                uint32_t vaddr = vs_u32 + (uint32_t)(vrow * 128)
                               + (uint32_t)(((vunit ^ (vrow & 7)) * 16));
                uint32_t b0, b1, b2, b3;
                ldsm4t(b0, b1, b2, b3, vaddr);
                mma_f16(o[2 * p][0], o[2 * p][1], o[2 * p][2], o[2 * p][3],
                        pa0, pa1, pa2, pa3, b0, b1);
                mma_f16(o[2 * p + 1][0], o[2 * p + 1][1], o[2 * p + 1][2], o[2 * p + 1][3],
                        pa0, pa1, pa2, pa3, b2, b3);
            }
        }
        __syncwarp();   // P reads done before next tile's P stores
    }

    // ---- normalize + write fp16 ----
    const float i0 = 1.0f / l0, i1 = 1.0f / l1;
    const int row0 = m0 + wrow + g;
    __half* ob0 = ao + ((size_t)(b * TSEQ + row0)) * CDIM + h * HD;
    __half* ob1 = ob0 + 8 * CDIM;
#pragma unroll
    for (int nj = 0; nj < 8; nj++) {
        *(__half2*)(ob0 + nj * 8 + 2 * t) =
            __floats2half2_rn(o[nj][0] * i0, o[nj][1] * i0);
        *(__half2*)(ob1 + nj * 8 + 2 * t) =
            __floats2half2_rn(o[nj][2] * i1, o[nj][3] * i1);
    }
}

// ---------------------------------------------------------------------------
// Host launcher
// ---------------------------------------------------------------------------
extern "C" void kernel_launch(void* const* d_in, const int* in_sizes, int n_in,
                              void* d_out, int out_size)
{
    const float* x       = (const float*)d_in[0];  // [2,2048,1024]
    const float* f_cos   = (const float*)d_in[1];  // [2048,32]
    const float* f_sin   = (const float*)d_in[2];  // [2048,32]
    const float* qkv_w   = (const float*)d_in[3];  // [3072,1024]
    const float* proj_w  = (const float*)d_in[4];  // [1024,1024]
    float* out = (float*)d_out;

    __half *qkv_ptr, *ao_ptr, *xr_ptr, *wq_ptr, *wp_ptr;
    cudaGetSymbolAddress((void**)&qkv_ptr, g_qkv);
    cudaGetSymbolAddress((void**)&ao_ptr,  g_ao);
    cudaGetSymbolAddress((void**)&xr_ptr,  g_xr);
    cudaGetSymbolAddress((void**)&wq_ptr,  g_wq);
    cudaGetSymbolAddress((void**)&wp_ptr,  g_wp);

    cudaFuncSetAttribute(gemm_f16_nt<0>,
                         cudaFuncAttributeMaxDynamicSharedMemorySize, GEMM_SMEM);
    cudaFuncSetAttribute(gemm_f16_nt<1>,
                         cudaFuncAttributeMaxDynamicSharedMemorySize, GEMM_SMEM);
    cudaFuncSetAttribute(attn_mma,
                         cudaFuncAttributeMaxDynamicSharedMemorySize, ATTN_SMEM);

    // 0) Convert x and weights to fp16
    to_fp16_kernel<<<1024, 256>>>((const float4*)x, (__half2*)xr_ptr,
                                  BT * CDIM / 4);
    to_fp16_kernel<<<1024, 256>>>((const float4*)qkv_w, (__half2*)wq_ptr,
                                  QKVDIM * CDIM / 4);
    to_fp16_kernel<<<1024, 256>>>((const float4*)proj_w, (__half2*)wp_ptr,
                                  CDIM * CDIM / 4);

    // 1) QKV projection with fused RoPE (+q scaling) epilogue, fp16 out
    {
        dim3 grid(QKVDIM / TN, BT / TM);
        gemm_f16_nt<1><<<grid, 256, GEMM_SMEM>>>(xr_ptr, wq_ptr, (void*)qkv_ptr,
                                                 BT, QKVDIM, CDIM,
                                                 f_cos, f_sin);
    }

    // 2) Causal flash attention (fp16 mma, exp2 softmax)
    {
        dim3 grid(TSEQ / AM, HEADS, BATCH);
        attn_mma<<<grid, 256, ATTN_SMEM>>>(qkv_ptr, ao_ptr);
    }

    // 3) Output projection (fp32 stores to d_out)
    {
        dim3 grid(CDIM / TN, BT / TM);
        gemm_f16_nt<0><<<grid, 256, GEMM_SMEM>>>(ao_ptr, wp_ptr, (void*)out,
                                                 BT, CDIM, CDIM,
                                                 nullptr, nullptr);
    }
}

// round 16
// speedup vs baseline: 8.8236x; 1.0617x over previous
#include <cuda_runtime.h>
#include <cuda_fp16.h>
#include <cstdint>
#include <math.h>

// Problem constants
#define BATCH   2
#define TSEQ    2048
#define CDIM    1024
#define HEADS   16
#define HD      64
#define BT      (BATCH * TSEQ)          // 4096 rows
#define QKVDIM  (3 * CDIM)              // 3072

// Scratch (allocation-free rule: __device__ globals) — fp16
__device__ __half g_qkv[(size_t)BT * QKVDIM];    // q(scaled,roped) k(roped) v
__device__ __half g_ao [(size_t)BT * CDIM];      // attention output
__device__ __half g_xr [(size_t)BT * CDIM];      // x, fp16
__device__ __half g_wq [(size_t)QKVDIM * CDIM];  // qkv_w, fp16
__device__ __half g_wp [(size_t)CDIM * CDIM];    // proj_w, fp16

#define QSCALE 0.1803368801111204f   // 0.125 * log2(e)

__device__ __forceinline__ uint32_t smem_u32(const void* p) {
    uint32_t a;
    asm("{ .reg .u64 t; cvta.to.shared.u64 t, %1; cvt.u32.u64 %0, t; }"
        : "=r"(a) : "l"(p));
    return a;
}
__device__ __forceinline__ void cp_async16(uint32_t dst, const void* src) {
    asm volatile("cp.async.cg.shared.global [%0], [%1], 16;"
                 :: "r"(dst), "l"(src));
}
__device__ __forceinline__ void ldsm4(uint32_t& r0, uint32_t& r1,
                                      uint32_t& r2, uint32_t& r3, uint32_t addr) {
    asm volatile("ldmatrix.sync.aligned.m8n8.x4.shared.b16 {%0,%1,%2,%3}, [%4];"
                 : "=r"(r0), "=r"(r1), "=r"(r2), "=r"(r3) : "r"(addr));
}
__device__ __forceinline__ void ldsm4t(uint32_t& r0, uint32_t& r1,
                                       uint32_t& r2, uint32_t& r3, uint32_t addr) {
    asm volatile("ldmatrix.sync.aligned.m8n8.x4.trans.shared.b16 {%0,%1,%2,%3}, [%4];"
                 : "=r"(r0), "=r"(r1), "=r"(r2), "=r"(r3) : "r"(addr));
}
// m16n8k16 fp16 -> fp32 accumulate
__device__ __forceinline__ void mma_f16(
    float& c0, float& c1, float& c2, float& c3,
    uint32_t a0, uint32_t a1, uint32_t a2, uint32_t a3,
    uint32_t b0, uint32_t b1)
{
    asm volatile(
        "mma.sync.aligned.m16n8k16.row.col.f32.f16.f16.f32 "
        "{%0,%1,%2,%3}, {%4,%5,%6,%7}, {%8,%9}, {%0,%1,%2,%3};"
        : "+f"(c0), "+f"(c1), "+f"(c2), "+f"(c3)
        : "r"(a0), "r"(a1), "r"(a2), "r"(a3), "r"(b0), "r"(b1));
}

// ---------------------------------------------------------------------------
// Single fused pre-convert pass: x, qkv_w, proj_w -> fp16
// ---------------------------------------------------------------------------
__global__ __launch_bounds__(256) void to_fp16_all(
    const float4* __restrict__ s0, __half2* __restrict__ d0, int n0,
    const float4* __restrict__ s1, __half2* __restrict__ d1, int n1,
    const float4* __restrict__ s2, __half2* __restrict__ d2, int n2)
{
    const int total = n0 + n1 + n2;
    for (int i = blockIdx.x * blockDim.x + threadIdx.x; i < total;
         i += gridDim.x * blockDim.x) {
        const float4* s; __half2* d; int j;
        if (i < n0)           { s = s0; d = d0; j = i; }
        else if (i < n0 + n1) { s = s1; d = d1; j = i - n0; }
        else                  { s = s2; d = d2; j = i - n0 - n1; }
        float4 v = s[j];
        d[2 * j]     = __floats2half2_rn(v.x, v.y);
        d[2 * j + 1] = __floats2half2_rn(v.z, v.w);
    }
}

// ---------------------------------------------------------------------------
// FP16 mma.sync GEMM, BK=64, 3-stage cp.async pipeline, ldmatrix fragments.
// MODE 0: plain fp32-store epilogue (proj GEMM, C = float*).
// MODE 1: fused RoPE epilogue, fp16 stores (QKV GEMM, C = half*);
//         q third additionally scaled by QSCALE.
// C[M,N] = A[M,K] @ B[N,K]^T. 128x128 CTA tile, 8 warps (4Mx2N).
// ---------------------------------------------------------------------------
#define TM  128
#define TN  128
#define BKF 64
#define SSTRH 72                         // halves; rows 4 banks apart -> ldsm ok
#define STGH (TM * SSTRH)                // halves per matrix stage (9216)
#define NSTAGE 3
#define GEMM_SMEM (NSTAGE * 2 * STGH * 2)   // 110,592 bytes

template <int MODE>
__global__ __launch_bounds__(256, 2) void gemm_f16_nt(
    const __half* __restrict__ A, const __half* __restrict__ B,
    void* __restrict__ Cv, int M, int N, int K,
    const float* __restrict__ cs, const float* __restrict__ sn)
{
    extern __shared__ __align__(16) __half smh[];

    const int tid  = threadIdx.x;
    const int wid  = tid >> 5;
    const int lane = tid & 31;
    const int g = lane >> 2;
    const int t = lane & 3;
    const int rl = lane & 7;
    const int wm = (wid & 3) * 32;
    const int wn = (wid >> 2) * 64;
    const int m0 = blockIdx.y * TM;
    const int n0 = blockIdx.x * TN;

    // ldmatrix lane-row decomposition
    const int a_row = wm + rl + ((lane & 8) ? 8 : 0);     // + mi*16
    const int a_k   = (lane & 16) ? 8 : 0;                // + ks
    const int b_row = wn + rl + ((lane & 16) ? 8 : 0);    // + p*16
    const int b_k   = (lane & 8) ? 8 : 0;                 // + ks

    float c[2][8][4];
#pragma unroll
    for (int mi = 0; mi < 2; mi++)
#pragma unroll
        for (int ni = 0; ni < 8; ni++)
#pragma unroll
            for (int r = 0; r < 4; r++) c[mi][ni][r] = 0.0f;

    const int nch = K / BKF;

    auto issue_load = [&](int s, int k0) {
        __half* As = smh + s * 2 * STGH;
        __half* Bs = As + STGH;
#pragma unroll
        for (int i = 0; i < 4; i++) {
            int e   = tid + i * 256;      // 0..1023
            int row = e >> 3;             // 0..127
            int u   = (e & 7) * 8;        // halves 0..56
            cp_async16(smem_u32(As + row * SSTRH + u),
                       A + (size_t)(m0 + row) * K + k0 + u);
            cp_async16(smem_u32(Bs + row * SSTRH + u),
                       B + (size_t)(n0 + row) * K + k0 + u);
        }
    };

    issue_load(0, 0);
    asm volatile("cp.async.commit_group;");
    if (nch > 1) issue_load(1, BKF);
    asm volatile("cp.async.commit_group;");

    for (int cch = 0; cch < nch; cch++) {
        asm volatile("cp.async.wait_group 1;");
        __syncthreads();
        if (cch + 2 < nch) issue_load((cch + 2) % NSTAGE, (cch + 2) * BKF);
        asm volatile("cp.async.commit_group;");

        const __half* As = smh + (cch % NSTAGE) * 2 * STGH;
        const __half* Bs = As + STGH;
        const uint32_t a_base = smem_u32(As) + (uint32_t)((a_row * SSTRH + a_k) * 2);
        const uint32_t b_base = smem_u32(Bs) + (uint32_t)((b_row * SSTRH + b_k) * 2);

#pragma unroll
        for (int ks8 = 0; ks8 < 4; ks8++) {
            const uint32_t ko = (uint32_t)(ks8 * 16 * 2);   // bytes
            uint32_t a[2][4];
#pragma unroll
            for (int mi = 0; mi < 2; mi++)
                ldsm4(a[mi][0], a[mi][1], a[mi][2], a[mi][3],
                      a_base + (uint32_t)(mi * 16 * SSTRH * 2) + ko);
            uint32_t b[8][2];
#pragma unroll
            for (int p = 0; p < 4; p++)
                ldsm4(b[2 * p][0], b[2 * p][1], b[2 * p + 1][0], b[2 * p + 1][1],
                      b_base + (uint32_t)(p * 16 * SSTRH * 2) + ko);
#pragma unroll
            for (int mi = 0; mi < 2; mi++)
#pragma unroll
                for (int ni = 0; ni < 8; ni++)
                    mma_f16(c[mi][ni][0], c[mi][ni][1], c[mi][ni][2], c[mi][ni][3],
                            a[mi][0], a[mi][1], a[mi][2], a[mi][3],
                            b[ni][0], b[ni][1]);
        }
    }

#pragma unroll
    for (int mi = 0; mi < 2; mi++) {
        const int row = m0 + wm + mi * 16 + g;
#pragma unroll
        for (int ni = 0; ni < 8; ni++) {
            const int col = n0 + wn + ni * 8 + 2 * t;
            float v0 = c[mi][ni][0], v1 = c[mi][ni][1];
            float v2 = c[mi][ni][2], v3 = c[mi][ni][3];
            if (MODE == 1) {
                if (col < 2 * CDIM) {     // q or k region: rotate pair
                    const int i  = (col & 63) >> 1;
                    const int t0 = row & (TSEQ - 1);
                    const int t1 = (row + 8) & (TSEQ - 1);
                    float c0v = __ldg(cs + t0 * 32 + i);
                    float s0v = __ldg(sn + t0 * 32 + i);
                    float c1v = __ldg(cs + t1 * 32 + i);
                    float s1v = __ldg(sn + t1 * 32 + i);
                    float r0 = v0 * c0v - v1 * s0v;
                    float r1 = v0 * s0v + v1 * c0v;
                    float r2 = v2 * c1v - v3 * s1v;
                    float r3 = v2 * s1v + v3 * c1v;
                    if (col < CDIM) {     // q: fold softmax scale
                        r0 *= QSCALE; r1 *= QSCALE; r2 *= QSCALE; r3 *= QSCALE;
                    }
                    v0 = r0; v1 = r1; v2 = r2; v3 = r3;
                }
                __half* Ch = (__half*)Cv;
                *(__half2*)(Ch + (size_t)row * N + col) = __floats2half2_rn(v0, v1);
                *(__half2*)(Ch + (size_t)(row + 8) * N + col) = __floats2half2_rn(v2, v3);
            } else {
                float* Cf = (float*)Cv;
                *(float2*)(Cf + (size_t)row * N + col) = make_float2(v0, v1);
                *(float2*)(Cf + (size_t)(row + 8) * N + col) = make_float2(v2, v3);
            }
        }
    }
}

// ---------------------------------------------------------------------------
// Flash attention, fp16 m16n8k16, double-buffered cp.async K/V, ldmatrix
// (+trans for V). Softmax via packed ex2.approx.f16x2 (2 exps per MUFU op);
// P stored as the same fp16 values summed into l (consistent normalization).
// ---------------------------------------------------------------------------
#define AM 128
#define AN 64
#define PBSTR 72                       // halves
#define KVSTGH (AN * 64)               // halves per K or V stage (4096 = 8KB)
#define ATTN_SMEM ((4 * KVSTGH + AM * PBSTR) * 2)   // 51,200 bytes

__global__ __launch_bounds__(256, 2) void attn_mma(
    const __half* __restrict__ qkv, __half* __restrict__ ao)
{
    extern __shared__ __align__(16) __half smA[];
    __half* Pb = smA + 4 * KVSTGH;      // [128][72] halves: Q staging, then P

    const int m0 = (gridDim.x - 1 - blockIdx.x) * AM;   // long-first
    const int h  = blockIdx.y;
    const int b  = blockIdx.z;
    const int tid = threadIdx.x;
    const int wid = tid >> 5, lane = tid & 31;
    const int g = lane >> 2, t = lane & 3;
    const int rl = lane & 7;
    const int wrow = wid * 16;

    const __half* kvb = qkv + (size_t)b * TSEQ * QKVDIM + CDIM + h * HD;

    auto issue_kv = [&](int s, int n0) {
        __half* Ks = smA + s * 2 * KVSTGH;
        __half* Vs = Ks + KVSTGH;
        const __half* kb = kvb + (size_t)n0 * QKVDIM;
        const __half* vb = kb + CDIM;
#pragma unroll
        for (int i = 0; i < 2; i++) {
            int e   = tid + i * 256;    // 0..511
            int row = e >> 3;
            int u   = e & 7;
            int u2  = u ^ (row & 7);    // 16B-unit XOR swizzle (8 units/row)
            cp_async16(smem_u32(Ks + row * 64 + u2 * 8),
                       kb + (size_t)row * QKVDIM + u * 8);
            cp_async16(smem_u32(Vs + row * 64 + u2 * 8),
                       vb + (size_t)row * QKVDIM + u * 8);
        }
    };

    const int ntiles = (m0 + AM) / AN;
    issue_kv(0, 0);
    asm volatile("cp.async.commit_group;");

    // ---- Stage Q via cp.async into Pb (already scaled + fp16) ----
    {
        const __half* qbase = qkv + ((size_t)(b * TSEQ + m0)) * QKVDIM + h * HD;
#pragma unroll
        for (int i = 0; i < 4; i++) {
            int e   = tid + i * 256;    // 0..1023
            int row = e >> 3;
            int u   = e & 7;
            cp_async16(smem_u32(Pb + row * PBSTR + u * 8),
                       qbase + (size_t)row * QKVDIM + u * 8);
        }
    }
    asm volatile("cp.async.commit_group;");
    asm volatile("cp.async.wait_group 0;");
    __syncthreads();

    // Q fragments: 4 k16-steps x 4 regs, via ldmatrix (A layout)
    const uint32_t pb_u32 = smem_u32(Pb);
    const uint32_t qrow_off =
        (uint32_t)(((wrow + rl + ((lane & 8) ? 8 : 0)) * PBSTR
                    + ((lane & 16) ? 8 : 0)) * 2);
    uint32_t qa[4][4];
#pragma unroll
    for (int ks8 = 0; ks8 < 4; ks8++)
        ldsm4(qa[ks8][0], qa[ks8][1], qa[ks8][2], qa[ks8][3],
              pb_u32 + qrow_off + (uint32_t)(ks8 * 16 * 2));

    float o[8][4];
#pragma unroll
    for (int nj = 0; nj < 8; nj++)
#pragma unroll
        for (int r = 0; r < 4; r++) o[nj][r] = 0.0f;
    float mx0 = -1e30f, mx1 = -1e30f, l0 = 0.0f, l1 = 0.0f;

    for (int kt = 0; kt < ntiles; kt++) {
        const int n0 = kt * AN;
        if (kt > 0) {
            asm volatile("cp.async.wait_group 0;");
            __syncthreads();
        }
        if (kt + 1 < ntiles) {
            issue_kv((kt + 1) & 1, n0 + AN);
            asm volatile("cp.async.commit_group;");
        }
        const __half* Ks = smA + (kt & 1) * 2 * KVSTGH;
        const __half* Vs = Ks + KVSTGH;
        const uint32_t ks_u32 = smem_u32(Ks);
        const uint32_t vs_u32 = smem_u32(Vs);

        // ---- S = Q K^T ----
        float s[8][4];
#pragma unroll
        for (int nj = 0; nj < 8; nj++)
#pragma unroll
            for (int r = 0; r < 4; r++) s[nj][r] = 0.0f;
#pragma unroll
        for (int ks8 = 0; ks8 < 4; ks8++) {
#pragma unroll
            for (int p = 0; p < 4; p++) {
                int krow = p * 16 + ((lane & 16) ? 8 : 0) + rl;
                int kunit = 2 * ks8 + ((lane & 8) ? 1 : 0);
                uint32_t kaddr = ks_u32 + (uint32_t)(krow * 128)
                               + (uint32_t)(((kunit ^ (krow & 7)) * 16));
                uint32_t b0, b1, b2, b3;
                ldsm4(b0, b1, b2, b3, kaddr);
                mma_f16(s[2 * p][0], s[2 * p][1], s[2 * p][2], s[2 * p][3],
                        qa[ks8][0], qa[ks8][1], qa[ks8][2], qa[ks8][3], b0, b1);
                mma_f16(s[2 * p + 1][0], s[2 * p + 1][1], s[2 * p + 1][2], s[2 * p + 1][3],
                        qa[ks8][0], qa[ks8][1], qa[ks8][2], qa[ks8][3], b2, b3);
            }
        }

        // ---- causal mask ----
        const int row0 = m0 + wrow + g;
        const int row1 = row0 + 8;
        if (n0 + AN - 1 > m0 + wrow) {
#pragma unroll
            for (int nj = 0; nj < 8; nj++) {
                int col = n0 + nj * 8 + 2 * t;
                if (col     > row0) s[nj][0] = -1e30f;
                if (col + 1 > row0) s[nj][1] = -1e30f;
                if (col     > row1) s[nj][2] = -1e30f;
                if (col + 1 > row1) s[nj][3] = -1e30f;
            }
        }

        // ---- online softmax (base-2, packed-half exp) ----
        float rm0 = -1e30f, rm1 = -1e30f;
#pragma unroll
        for (int nj = 0; nj < 8; nj++) {
            rm0 = fmaxf(rm0, fmaxf(s[nj][0], s[nj][1]));
            rm1 = fmaxf(rm1, fmaxf(s[nj][2], s[nj][3]));
        }
        rm0 = fmaxf(rm0, __shfl_xor_sync(0xffffffffu, rm0, 1));
        rm0 = fmaxf(rm0, __shfl_xor_sync(0xffffffffu, rm0, 2));
        rm1 = fmaxf(rm1, __shfl_xor_sync(0xffffffffu, rm1, 1));
        rm1 = fmaxf(rm1, __shfl_xor_sync(0xffffffffu, rm1, 2));
        float nm0 = fmaxf(mx0, rm0), nm1 = fmaxf(mx1, rm1);
        float al0 = exp2f(mx0 - nm0), al1 = exp2f(mx1 - nm1);
        mx0 = nm0; mx1 = nm1;

        float rs0 = 0.0f, rs1 = 0.0f;
#pragma unroll
        for (int nj = 0; nj < 8; nj++) {
            __half2 e01 = h2exp2(__floats2half2_rn(s[nj][0] - nm0, s[nj][1] - nm0));
            __half2 e23 = h2exp2(__floats2half2_rn(s[nj][2] - nm1, s[nj][3] - nm1));
            *(__half2*)(Pb + (wrow + g) * PBSTR + nj * 8 + 2 * t) = e01;
            *(__half2*)(Pb + (wrow + g + 8) * PBSTR + nj * 8 + 2 * t) = e23;
            float2 f01 = __half22float2(e01);
            float2 f23 = __half22float2(e23);
            rs0 += f01.x + f01.y;
            rs1 += f23.x + f23.y;
        }
        rs0 += __shfl_xor_sync(0xffffffffu, rs0, 1);
        rs0 += __shfl_xor_sync(0xffffffffu, rs0, 2);
        rs1 += __shfl_xor_sync(0xffffffffu, rs1, 1);
        rs1 += __shfl_xor_sync(0xffffffffu, rs1, 2);
        l0 = l0 * al0 + rs0;
        l1 = l1 * al1 + rs1;
#pragma unroll
        for (int nj = 0; nj < 8; nj++) {
            o[nj][0] *= al0; o[nj][1] *= al0;
            o[nj][2] *= al1; o[nj][3] *= al1;
        }
        __syncwarp();   // P visible warp-wide (warp-private rows)

        // ---- O += P V ----
#pragma unroll
        for (int kp = 0; kp < 4; kp++) {
            uint32_t pa0, pa1, pa2, pa3;
            ldsm4(pa0, pa1, pa2, pa3,
                  pb_u32 + qrow_off + (uint32_t)(kp * 16 * 2));
#pragma unroll
            for (int p = 0; p < 4; p++) {
                int vrow = kp * 16 + ((lane & 8) ? 8 : 0) + rl;
                int vunit = 2 * p + ((lane & 16) ? 1 : 0);
                uint32_t vaddr = vs_u32 + (uint32_t)(vrow * 128)
                               + (uint32_t)(((vunit ^ (vrow & 7)) * 16));
                uint32_t b0, b1, b2, b3;
                ldsm4t(b0, b1, b2, b3, vaddr);
                mma_f16(o[2 * p][0], o[2 * p][1], o[2 * p][2], o[2 * p][3],
                        pa0, pa1, pa2, pa3, b0, b1);
                mma_f16(o[2 * p + 1][0], o[2 * p + 1][1], o[2 * p + 1][2], o[2 * p + 1][3],
                        pa0, pa1, pa2, pa3, b2, b3);
            }
        }
        __syncwarp();   // P reads done before next tile's P stores
    }

    // ---- normalize + write fp16 ----
    const float i0 = 1.0f / l0, i1 = 1.0f / l1;
    const int row0 = m0 + wrow + g;
    __half* ob0 = ao + ((size_t)(b * TSEQ + row0)) * CDIM + h * HD;
    __half* ob1 = ob0 + 8 * CDIM;
#pragma unroll
    for (int nj = 0; nj < 8; nj++) {
        *(__half2*)(ob0 + nj * 8 + 2 * t) =
            __floats2half2_rn(o[nj][0] * i0, o[nj][1] * i0);
        *(__half2*)(ob1 + nj * 8 + 2 * t) =
            __floats2half2_rn(o[nj][2] * i1, o[nj][3] * i1);
    }
}

// ---------------------------------------------------------------------------
// Host launcher
// ---------------------------------------------------------------------------
extern "C" void kernel_launch(void* const* d_in, const int* in_sizes, int n_in,
                              void* d_out, int out_size)
{
    const float* x       = (const float*)d_in[0];  // [2,2048,1024]
    const float* f_cos   = (const float*)d_in[1];  // [2048,32]
    const float* f_sin   = (const float*)d_in[2];  // [2048,32]
    const float* qkv_w   = (const float*)d_in[3];  // [3072,1024]
    const float* proj_w  = (const float*)d_in[4];  // [1024,1024]
    float* out = (float*)d_out;

    __half *qkv_ptr, *ao_ptr, *xr_ptr, *wq_ptr, *wp_ptr;
    cudaGetSymbolAddress((void**)&qkv_ptr, g_qkv);
    cudaGetSymbolAddress((void**)&ao_ptr,  g_ao);
    cudaGetSymbolAddress((void**)&xr_ptr,  g_xr);
    cudaGetSymbolAddress((void**)&wq_ptr,  g_wq);
    cudaGetSymbolAddress((void**)&wp_ptr,  g_wp);

    cudaFuncSetAttribute(gemm_f16_nt<0>,
                         cudaFuncAttributeMaxDynamicSharedMemorySize, GEMM_SMEM);
    cudaFuncSetAttribute(gemm_f16_nt<1>,
                         cudaFuncAttributeMaxDynamicSharedMemorySize, GEMM_SMEM);
    cudaFuncSetAttribute(attn_mma,
                         cudaFuncAttributeMaxDynamicSharedMemorySize, ATTN_SMEM);

    // 0) Convert x and both weights to fp16 (single launch)
    to_fp16_all<<<1024, 256>>>(
        (const float4*)x,      (__half2*)xr_ptr, BT * CDIM / 4,
        (const float4*)qkv_w,  (__half2*)wq_ptr, QKVDIM * CDIM / 4,
        (const float4*)proj_w, (__half2*)wp_ptr, CDIM * CDIM / 4);

    // 1) QKV projection with fused RoPE (+q scaling) epilogue, fp16 out
    {
        dim3 grid(QKVDIM / TN, BT / TM);
        gemm_f16_nt<1><<<grid, 256, GEMM_SMEM>>>(xr_ptr, wq_ptr, (void*)qkv_ptr,
                                                 BT, QKVDIM, CDIM,
                                                 f_cos, f_sin);
    }

    // 2) Causal flash attention (fp16 mma, packed-half exp2 softmax)
    {
        dim3 grid(TSEQ / AM, HEADS, BATCH);
        attn_mma<<<grid, 256, ATTN_SMEM>>>(qkv_ptr, ao_ptr);
    }

    // 3) Output projection (fp32 stores to d_out)
    {
        dim3 grid(CDIM / TN, BT / TM);
        gemm_f16_nt<0><<<grid, 256, GEMM_SMEM>>>(ao_ptr, wp_ptr, (void*)out,
                                                 BT, CDIM, CDIM,
                                                 nullptr, nullptr);
    }
}